// round 12
// baseline (speedup 1.0000x reference)
#include <cuda_runtime.h>
#include <cuda_fp16.h>

// Problem constants (fixed by the dataset)
#define NN 50000
#define EE 800000
#define ETOT 850000   // EE + NN self-loops
#define HH 4
#define CC 32
#define HC 128        // HH*CC
#define NBLK ((NN + 1023) / 1024)   // 49 scan blocks

// ---------------- scratch (device globals: allocation-free) ----------------
__device__ __align__(16) __half g_lin16[2][NN * HC];  // messages (fp16)
__device__ float g_alsrc[2][NN * HH];
__device__ float g_aldst[2][NN * HH];
__device__ float g_act[NN * HC];
__device__ __align__(16) float g_gmax[12];
__device__ int   g_csrc[ETOT];
__device__ int   g_rowptr[NN + 1];
__device__ int   g_fill[NN];
__device__ int   g_bsum[64];
__device__ int   g_is64;

// ---------------- streams/events for fork/join --------------
struct StreamPack {
    cudaStream_t sA, sB;
    cudaEvent_t evFork, evA, evB;
    StreamPack() {
        cudaStreamCreateWithFlags(&sA, cudaStreamNonBlocking);
        cudaStreamCreateWithFlags(&sB, cudaStreamNonBlocking);
        cudaEventCreateWithFlags(&evFork, cudaEventDisableTiming);
        cudaEventCreateWithFlags(&evA, cudaEventDisableTiming);
        cudaEventCreateWithFlags(&evB, cudaEventDisableTiming);
    }
};
static StreamPack g_sp;

__device__ __forceinline__ void atomicMaxF(float* addr, float v) {
    if (v >= 0.f) atomicMax((int*)addr, __float_as_int(v));
    else          atomicMin((unsigned int*)addr, __float_as_uint(v));
}

// ---- packed f32x2 helpers (FFMA2 path, sm_103a) ----
__device__ __forceinline__ unsigned long long pack2(float x) {
    unsigned long long r;
    asm("mov.b64 %0, {%1, %2};" : "=l"(r) : "f"(x), "f"(x));
    return r;
}
__device__ __forceinline__ void fma2(unsigned long long& d, unsigned long long a,
                                     unsigned long long b) {
    asm("fma.rn.f32x2 %0, %1, %2, %0;" : "+l"(d) : "l"(a), "l"(b));
}
__device__ __forceinline__ float2 unpack2(unsigned long long v) {
    float lo, hi;
    asm("mov.b64 {%0, %1}, %2;" : "=f"(lo), "=f"(hi) : "l"(v));
    return make_float2(lo, hi);
}

// ---------------- edge prep ----------------
__global__ void detect_kernel(const int* __restrict__ buf) {
    if (blockIdx.x == 0 && threadIdx.x == 0) {
        int orv = 0;
        #pragma unroll
        for (int i = 1; i < 64; i += 2) orv |= buf[i];
        g_is64 = (orv == 0) ? 1 : 0;
    }
    if (blockIdx.x == 0 && threadIdx.x < 12) g_gmax[threadIdx.x] = -3.0e38f;
}

__global__ void zero_fill_kernel() {
    int t = blockIdx.x * blockDim.x + threadIdx.x;
    if (t < NN) g_fill[t] = 0;
}

// degree count: decode dst directly from the input buffer
__global__ void count_kernel(const int* __restrict__ buf) {
    int t = blockIdx.x * blockDim.x + threadIdx.x;
    if (t >= ETOT) return;
    int d;
    if (t < EE) {
        d = g_is64 ? buf[2 * (EE + t)] : buf[EE + t];
    } else {
        d = t - EE;
    }
    atomicAdd(&g_fill[d], 1);
}

// ---------------- 3-phase coalesced scan ----------------
__global__ void block_sum_kernel() {
    __shared__ int ws[32];
    int tid = threadIdx.x;
    int idx = blockIdx.x * 1024 + tid;
    int v = (idx < NN) ? g_fill[idx] : 0;
    #pragma unroll
    for (int o = 16; o >= 1; o >>= 1) v += __shfl_xor_sync(0xffffffff, v, o);
    int lane = tid & 31, wid = tid >> 5;
    if (lane == 0) ws[wid] = v;
    __syncthreads();
    if (wid == 0) {
        int w = ws[lane];
        #pragma unroll
        for (int o = 16; o >= 1; o >>= 1) w += __shfl_xor_sync(0xffffffff, w, o);
        if (lane == 0) g_bsum[blockIdx.x] = w;
    }
}

__global__ void scan_bsum_kernel() {
    __shared__ int sm[64];
    int tid = threadIdx.x;
    int v = (tid < NBLK) ? g_bsum[tid] : 0;
    sm[tid] = v;
    __syncthreads();
    #pragma unroll
    for (int o = 1; o < 64; o <<= 1) {
        int t2 = (tid >= o) ? sm[tid - o] : 0;
        __syncthreads();
        sm[tid] += t2;
        __syncthreads();
    }
    if (tid < NBLK) g_bsum[tid] = sm[tid] - v;
}

__global__ void rowptr_kernel() {
    __shared__ int ws[32];
    int tid = threadIdx.x;
    int idx = blockIdx.x * 1024 + tid;
    int lane = tid & 31, wid = tid >> 5;
    int c = (idx < NN) ? g_fill[idx] : 0;
    int v = c;
    #pragma unroll
    for (int o = 1; o < 32; o <<= 1) {
        int t2 = __shfl_up_sync(0xffffffff, v, o);
        if (lane >= o) v += t2;
    }
    if (lane == 31) ws[wid] = v;
    __syncthreads();
    if (wid == 0) {
        int w = ws[lane];
        #pragma unroll
        for (int o = 1; o < 32; o <<= 1) {
            int t2 = __shfl_up_sync(0xffffffff, w, o);
            if (lane >= o) w += t2;
        }
        ws[lane] = w;
    }
    __syncthreads();
    int excl = v - c + (wid > 0 ? ws[wid - 1] : 0) + g_bsum[blockIdx.x];
    if (idx < NN) {
        g_rowptr[idx] = excl;
        g_fill[idx] = excl;
    }
    if (idx == 0) g_rowptr[NN] = ETOT;
}

// fill CSR: decode both endpoints directly from the input buffer
__global__ void csr_fill_kernel(const int* __restrict__ buf) {
    int t = blockIdx.x * blockDim.x + threadIdx.x;
    if (t >= ETOT) return;
    int s, d;
    if (t < EE) {
        if (g_is64) {
            s = buf[2 * t];
            d = buf[2 * (EE + t)];
        } else {
            s = buf[t];
            d = buf[EE + t];
        }
    } else {
        s = d = t - EE;
    }
    int pos = atomicAdd(&g_fill[d], 1);
    g_csrc[pos] = s;
}

// ---------------- GEMM (FFMA2) + fused attention logits ----------------
template<int OUT, bool FROMACT>
__global__ __launch_bounds__(128) void gemm_al_kernel(
        const float* __restrict__ X, const float* __restrict__ W,
        const float* __restrict__ a_src, const float* __restrict__ a_dst,
        int gslot, int obuf) {
    constexpr int NPB = (OUT == 128) ? 64 : 128;
    constexpr int CPT = (OUT == 128) ? 8 : 4;
    constexpr int CP2 = CPT / 2;
    constexpr int CGN = OUT / CPT;
    constexpr int KC  = 32;
    constexpr int NH  = (OUT == 128) ? 4 : 1;

    __shared__ __align__(16) float Xs[KC][NPB];
    __shared__ __align__(16) float Ws[KC][OUT];
    __shared__ float smax[NH];

    const float* __restrict__ Xp = FROMACT ? g_act : X;
    __half* __restrict__ lin = &g_lin16[obuf][0];
    float* __restrict__ alsrc = &g_alsrc[obuf][0];
    float* __restrict__ aldst = &g_aldst[obuf][0];

    const int tid = threadIdx.x;
    const int cg = tid % CGN;
    const int ng = tid / CGN;
    const int row0 = blockIdx.x * NPB;

    if (tid < NH) smax[tid] = -3.0e38f;

    unsigned long long acc2[8][CP2];
    #pragma unroll
    for (int i = 0; i < 8; i++)
        #pragma unroll
        for (int j = 0; j < CP2; j++) acc2[i][j] = 0ull;

    for (int kc = 0; kc < HC; kc += KC) {
        __syncthreads();
        #pragma unroll
        for (int e = tid; e < KC * NPB / 4; e += 128) {
            int n  = e / (KC / 4);
            int kq = e % (KC / 4);
            int row = row0 + n; if (row >= NN) row = NN - 1;
            float4 v = *(const float4*)&Xp[row * HC + kc + kq * 4];
            Xs[kq * 4 + 0][n] = v.x;
            Xs[kq * 4 + 1][n] = v.y;
            Xs[kq * 4 + 2][n] = v.z;
            Xs[kq * 4 + 3][n] = v.w;
        }
        #pragma unroll
        for (int e = tid; e < KC * OUT / 4; e += 128) {
            ((float4*)&Ws[0][0])[e] = ((const float4*)&W[kc * OUT])[e];
        }
        __syncthreads();

        #pragma unroll
        for (int k = 0; k < KC; k++) {
            float4 xa = *(const float4*)&Xs[k][ng * 8];
            float4 xb = *(const float4*)&Xs[k][ng * 8 + 4];
            unsigned long long xd[8];
            xd[0] = pack2(xa.x); xd[1] = pack2(xa.y);
            xd[2] = pack2(xa.z); xd[3] = pack2(xa.w);
            xd[4] = pack2(xb.x); xd[5] = pack2(xb.y);
            xd[6] = pack2(xb.z); xd[7] = pack2(xb.w);

            unsigned long long wp[CP2];
            {
                double2 w0 = *(const double2*)&Ws[k][cg * CPT];
                wp[0] = __double_as_longlong(w0.x);
                wp[1] = __double_as_longlong(w0.y);
                if (CP2 == 4) {
                    double2 w1 = *(const double2*)&Ws[k][cg * CPT + 4];
                    wp[2] = __double_as_longlong(w1.x);
                    wp[3] = __double_as_longlong(w1.y);
                }
            }
            #pragma unroll
            for (int i = 0; i < 8; i++)
                #pragma unroll
                for (int j = 0; j < CP2; j++)
                    fma2(acc2[i][j], xd[i], wp[j]);
        }
    }

    float acc[8][CPT];
    #pragma unroll
    for (int i = 0; i < 8; i++)
        #pragma unroll
        for (int j = 0; j < CP2; j++) {
            float2 v = unpack2(acc2[i][j]);
            acc[i][2 * j] = v.x;
            acc[i][2 * j + 1] = v.y;
        }

    // store messages as fp16 (half2 pairs)
    #pragma unroll
    for (int i = 0; i < 8; i++) {
        int row = row0 + ng * 8 + i;
        if (row < NN) {
            #pragma unroll
            for (int j = 0; j < CP2; j++) {
                __half2 h = __float22half2_rn(make_float2(acc[i][2 * j], acc[i][2 * j + 1]));
                *(__half2*)&lin[row * OUT + cg * CPT + 2 * j] = h;
            }
        }
    }

    // ---- fused al ----
    float asv[CPT], adv[CPT];
    {
        float4 a0 = *(const float4*)&a_src[cg * CPT];
        asv[0] = a0.x; asv[1] = a0.y; asv[2] = a0.z; asv[3] = a0.w;
        float4 d0 = *(const float4*)&a_dst[cg * CPT];
        adv[0] = d0.x; adv[1] = d0.y; adv[2] = d0.z; adv[3] = d0.w;
        if (CPT == 8) {
            float4 a1 = *(const float4*)&a_src[cg * CPT + 4];
            asv[4] = a1.x; asv[5] = a1.y; asv[6] = a1.z; asv[7] = a1.w;
            float4 d1 = *(const float4*)&a_dst[cg * CPT + 4];
            adv[4] = d1.x; adv[5] = d1.y; adv[6] = d1.z; adv[7] = d1.w;
        }
    }
    float ssp[8], sdp[8];
    #pragma unroll
    for (int i = 0; i < 8; i++) {
        float ss = 0.f, sd = 0.f;
        #pragma unroll
        for (int j = 0; j < CPT; j++) {
            ss += acc[i][j] * asv[j];
            sd += acc[i][j] * adv[j];
        }
        ssp[i] = ss; sdp[i] = sd;
    }
    #pragma unroll
    for (int i = 0; i < 8; i++) {
        ssp[i] += __shfl_xor_sync(0xffffffff, ssp[i], 1);
        sdp[i] += __shfl_xor_sync(0xffffffff, sdp[i], 1);
        ssp[i] += __shfl_xor_sync(0xffffffff, ssp[i], 2);
        sdp[i] += __shfl_xor_sync(0xffffffff, sdp[i], 2);
        if (OUT == 32) {
            ssp[i] += __shfl_xor_sync(0xffffffff, ssp[i], 4);
            sdp[i] += __shfl_xor_sync(0xffffffff, sdp[i], 4);
        }
    }
    float lmax = -3.0e38f;
    if (OUT == 128) {
        if ((cg & 3) == 0) {
            int h = cg >> 2;
            #pragma unroll
            for (int i = 0; i < 8; i++) {
                int row = row0 + ng * 8 + i;
                if (row < NN) {
                    alsrc[row * HH + h] = ssp[i];
                    aldst[row * HH + h] = sdp[i];
                    lmax = fmaxf(lmax, ssp[i]);
                }
            }
            atomicMaxF(&smax[h], lmax);
        }
    } else {
        if (cg == 0) {
            #pragma unroll
            for (int i = 0; i < 8; i++) {
                int row = row0 + ng * 8 + i;
                if (row < NN) {
                    alsrc[row] = ssp[i];
                    aldst[row] = sdp[i];
                    lmax = fmaxf(lmax, ssp[i]);
                }
            }
            atomicMaxF(&smax[0], lmax);
        }
    }
    __syncthreads();
    if (tid < NH) atomicMaxF(&g_gmax[gslot + tid], smax[tid]);
}

// ---------------- fused GAT aggregation: 2 warps (64 threads) per dst node ----
// Reads buffer `ibuf`, writes g_act. 256-thr block = 4 nodes.
__global__ __launch_bounds__(256) void gat_agg4_kernel(const float* __restrict__ b,
                                                       int gslot, int ibuf) {
    __shared__ int    ss[8][32];
    __shared__ float4 ww[8][32];
    __shared__ float  comb[4][32][8];   // warp-1 partials: a0x,a0y,a1x,a1y,denom4

    int tid = threadIdx.x;
    int node = blockIdx.x * 4 + (tid >> 6);   // 4 nodes per block; NN%4==0
    int lane = tid & 31;
    int p = (tid >> 5) & 1;                   // warp within pair
    int nb = tid >> 6;                        // node within block
    int wslot = tid >> 5;
    int start = g_rowptr[node], end = g_rowptr[node + 1];

    const __half* __restrict__ lin = &g_lin16[ibuf][0];
    const float* __restrict__ alsrc = &g_alsrc[ibuf][0];

    float4 ad = *(const float4*)&g_aldst[ibuf][node * HH];
    float4 gm = *(const float4*)&g_gmax[gslot];
    float4 m;
    m.x = gm.x + ad.x; m.x = (m.x > 0.f) ? m.x : 0.2f * m.x;
    m.y = gm.y + ad.y; m.y = (m.y > 0.f) ? m.y : 0.2f * m.y;
    m.z = gm.z + ad.z; m.z = (m.z > 0.f) ? m.z : 0.2f * m.z;
    m.w = gm.w + ad.w; m.w = (m.w > 0.f) ? m.w : 0.2f * m.w;

    const int h0 = lane >> 4;
    const int h1 = 2 + h0;

    float4 denom = make_float4(0.f, 0.f, 0.f, 0.f);
    float a0x = 0.f, a0y = 0.f, a1x = 0.f, a1y = 0.f;

    // this warp handles alternating 32-edge chunks
    for (int base = start + p * 32; base < end; base += 64) {
        int i = base + lane;
        float4 w = make_float4(0.f, 0.f, 0.f, 0.f);
        int s = 0;
        if (i < end) {
            s = g_csrc[i];
            float4 v = *(const float4*)&alsrc[s * HH];
            v.x += ad.x; v.y += ad.y; v.z += ad.z; v.w += ad.w;
            v.x = (v.x > 0.f) ? v.x : 0.2f * v.x;
            v.y = (v.y > 0.f) ? v.y : 0.2f * v.y;
            v.z = (v.z > 0.f) ? v.z : 0.2f * v.z;
            v.w = (v.w > 0.f) ? v.w : 0.2f * v.w;
            w.x = __expf(v.x - m.x);
            w.y = __expf(v.y - m.y);
            w.z = __expf(v.z - m.z);
            w.w = __expf(v.w - m.w);
        }
        denom.x += w.x; denom.y += w.y; denom.z += w.z; denom.w += w.w;
        ss[wslot][lane] = s;
        ww[wslot][lane] = w;
        __syncwarp();
        int n = min(32, end - base);
        for (int j = 0; j < n; j++) {
            int sj = ss[wslot][j];
            const float* wjp = (const float*)&ww[wslot][j];
            float w0 = wjp[h0];
            float w1 = wjp[h1];
            const __half2* hp = (const __half2*)(lin + sj * HC);
            float2 m0 = __half22float2(hp[lane]);
            float2 m1 = __half22float2(hp[32 + lane]);
            a0x += w0 * m0.x; a0y += w0 * m0.y;
            a1x += w1 * m1.x; a1y += w1 * m1.y;
        }
        __syncwarp();
    }

    // combine warp 1 -> warp 0 (per-lane channel partials + denom)
    if (p == 1) {
        comb[nb][lane][0] = a0x; comb[nb][lane][1] = a0y;
        comb[nb][lane][2] = a1x; comb[nb][lane][3] = a1y;
        comb[nb][lane][4] = denom.x; comb[nb][lane][5] = denom.y;
        comb[nb][lane][6] = denom.z; comb[nb][lane][7] = denom.w;
    }
    __syncthreads();
    if (p == 1) return;

    a0x += comb[nb][lane][0]; a0y += comb[nb][lane][1];
    a1x += comb[nb][lane][2]; a1y += comb[nb][lane][3];
    denom.x += comb[nb][lane][4]; denom.y += comb[nb][lane][5];
    denom.z += comb[nb][lane][6]; denom.w += comb[nb][lane][7];

    #pragma unroll
    for (int o = 16; o >= 1; o >>= 1) {
        denom.x += __shfl_xor_sync(0xffffffff, denom.x, o);
        denom.y += __shfl_xor_sync(0xffffffff, denom.y, o);
        denom.z += __shfl_xor_sync(0xffffffff, denom.z, o);
        denom.w += __shfl_xor_sync(0xffffffff, denom.w, o);
    }
    float rd0 = 1.f / ((h0 == 0 ? denom.x : denom.y) + 1e-16f);
    float rd1 = 1.f / ((h1 == 2 ? denom.z : denom.w) + 1e-16f);

    float2 b0 = *(const float2*)&b[2 * lane];
    float2 b1 = *(const float2*)&b[64 + 2 * lane];
    a0x = a0x * rd0 + b0.x;
    a0y = a0y * rd0 + b0.y;
    a1x = a1x * rd1 + b1.x;
    a1y = a1y * rd1 + b1.y;
    // ELU
    a0x = (a0x > 0.f) ? a0x : (__expf(a0x) - 1.f);
    a0y = (a0y > 0.f) ? a0y : (__expf(a0y) - 1.f);
    a1x = (a1x > 0.f) ? a1x : (__expf(a1x) - 1.f);
    a1y = (a1y > 0.f) ? a1y : (__expf(a1y) - 1.f);

    float* o = g_act + node * HC;
    *(float2*)&o[2 * lane] = make_float2(a0x, a0y);
    *(float2*)&o[64 + 2 * lane] = make_float2(a1x, a1y);
}

// layer 3 (H=1): 2 warps per node, fused classifier head + embedding (reads buf 0)
__global__ __launch_bounds__(256) void gat_agg1_head_kernel(
        const float* __restrict__ b, const float* __restrict__ Wc,
        const float* __restrict__ bc, float* __restrict__ out) {
    __shared__ int   ss[8][32];
    __shared__ float ww[8][32];
    __shared__ float comb[4][32][2];

    int tid = threadIdx.x;
    int node = blockIdx.x * 4 + (tid >> 6);
    int lane = tid & 31;
    int p = (tid >> 5) & 1;
    int nb = tid >> 6;
    int wslot = tid >> 5;
    int start = g_rowptr[node], end = g_rowptr[node + 1];

    const __half* __restrict__ lin = &g_lin16[0][0];
    const float* __restrict__ alsrc = &g_alsrc[0][0];

    float ad = g_aldst[0][node];
    float gm = g_gmax[8];
    float m = gm + ad; m = (m > 0.f) ? m : 0.2f * m;

    float denom = 0.f;
    float acc = 0.f;

    for (int base = start + p * 32; base < end; base += 64) {
        int i = base + lane;
        float w = 0.f;
        int s = 0;
        if (i < end) {
            s = g_csrc[i];
            float v = alsrc[s] + ad;
            v = (v > 0.f) ? v : 0.2f * v;
            w = __expf(v - m);
        }
        denom += w;
        ss[wslot][lane] = s;
        ww[wslot][lane] = w;
        __syncwarp();
        int n = min(32, end - base);
        for (int j = 0; j < n; j++) {
            acc += ww[wslot][j] * __half2float(lin[ss[wslot][j] * CC + lane]);
        }
        __syncwarp();
    }

    if (p == 1) {
        comb[nb][lane][0] = acc;
        comb[nb][lane][1] = denom;
    }
    __syncthreads();
    if (p == 1) return;

    acc += comb[nb][lane][0];
    denom += comb[nb][lane][1];

    #pragma unroll
    for (int o = 16; o >= 1; o >>= 1)
        denom += __shfl_xor_sync(0xffffffff, denom, o);

    float h = acc / (denom + 1e-16f) + b[lane];

    out[NN * 2 + node * CC + lane] = h;

    float o0 = h * Wc[lane * 2 + 0];
    float o1 = h * Wc[lane * 2 + 1];
    #pragma unroll
    for (int o = 16; o >= 1; o >>= 1) {
        o0 += __shfl_xor_sync(0xffffffff, o0, o);
        o1 += __shfl_xor_sync(0xffffffff, o1, o);
    }
    if (lane == 0) {
        out[node * 2 + 0] = o0 + bc[0];
        out[node * 2 + 1] = o1 + bc[1];
    }
}

// ---------------- launch ----------------
extern "C" void kernel_launch(void* const* d_in, const int* in_sizes, int n_in,
                              void* d_out, int out_size) {
    const float* x   = (const float*)d_in[0];
    const int*   ei  = (const int*)d_in[1];
    const float* W1  = (const float*)d_in[2];
    const float* a1s = (const float*)d_in[3];
    const float* a1d = (const float*)d_in[4];
    const float* b1  = (const float*)d_in[5];
    const float* W2  = (const float*)d_in[6];
    const float* a2s = (const float*)d_in[7];
    const float* a2d = (const float*)d_in[8];
    const float* b2  = (const float*)d_in[9];
    const float* W3  = (const float*)d_in[10];
    const float* a3s = (const float*)d_in[11];
    const float* a3d = (const float*)d_in[12];
    const float* b3  = (const float*)d_in[13];
    const float* Wc  = (const float*)d_in[14];
    const float* bc  = (const float*)d_in[15];
    float* out = (float*)d_out;

    const int T = 256;
    const int gE = (ETOT + T - 1) / T;
    const int gN = (NN + T - 1) / T;
    const int gW2 = NN / 4;             // 2 warps per node, 4 nodes per 256-thr block

    cudaStream_t s0 = 0;                // capture-origin stream
    cudaStream_t sA = g_sp.sA;          // CSR branch
    cudaStream_t sB = g_sp.sB;          // GEMM1 branch

    // shared prologue on the capture stream
    detect_kernel<<<1, 32, 0, s0>>>(ei);

    // fork
    cudaEventRecord(g_sp.evFork, s0);
    cudaStreamWaitEvent(sA, g_sp.evFork, 0);
    cudaStreamWaitEvent(sB, g_sp.evFork, 0);

    // ---- branch A: CSR build ----
    zero_fill_kernel<<<gN, T, 0, sA>>>();
    count_kernel<<<gE, T, 0, sA>>>(ei);
    block_sum_kernel<<<NBLK, 1024, 0, sA>>>();
    scan_bsum_kernel<<<1, 64, 0, sA>>>();
    rowptr_kernel<<<NBLK, 1024, 0, sA>>>();
    csr_fill_kernel<<<gE, T, 0, sA>>>(ei);
    cudaEventRecord(g_sp.evA, sA);

    // ---- branch B: layer-1 GEMM + attention logits (writes buf 0) ----
    gemm_al_kernel<128, false><<<(NN + 63) / 64, 128, 0, sB>>>(x, W1, a1s, a1d, 0, 0);
    cudaEventRecord(g_sp.evB, sB);

    // join on the capture stream
    cudaStreamWaitEvent(s0, g_sp.evA, 0);
    cudaStreamWaitEvent(s0, g_sp.evB, 0);

    // ---- serial layer chain (R8 schedule — overlap within layers regressed) ----
    gat_agg4_kernel<<<gW2, T, 0, s0>>>(b1, 0, 0);
    gemm_al_kernel<128, true><<<(NN + 63) / 64, 128, 0, s0>>>(nullptr, W2, a2s, a2d, 4, 1);
    gat_agg4_kernel<<<gW2, T, 0, s0>>>(b2, 4, 1);
    gemm_al_kernel<32, true><<<(NN + 127) / 128, 128, 0, s0>>>(nullptr, W3, a3s, a3d, 8, 0);
    gat_agg1_head_kernel<<<gW2, T, 0, s0>>>(b3, Wc, bc, out);
}

// round 13
// speedup vs baseline: 1.3337x; 1.3337x over previous
#include <cuda_runtime.h>
#include <cuda_fp16.h>

// Problem constants (fixed by the dataset)
#define NN 50000
#define EE 800000
#define ETOT 850000   // EE + NN self-loops
#define HH 4
#define CC 32
#define HC 128        // HH*CC
#define NBLK ((NN + 1023) / 1024)   // 49 scan blocks

// ---------------- scratch (device globals: allocation-free) ----------------
__device__ __align__(16) __half g_lin16[NN * HC];  // messages (fp16, gather-only)
__device__ float g_act[NN * HC];
__device__ float g_alsrc[NN * HH];
__device__ float g_aldst[NN * HH];
__device__ __align__(16) float g_gmax[12];
__device__ int   g_csrc[ETOT];
__device__ int   g_rowptr[NN + 1];
__device__ int   g_fill[NN];
__device__ int   g_bsum[64];
__device__ int   g_is64;

// ---------------- streams for fork/join inside graph capture --------------
struct StreamPack {
    cudaStream_t sA, sB;
    cudaEvent_t evFork, evA, evB;
    StreamPack() {
        cudaStreamCreateWithFlags(&sA, cudaStreamNonBlocking);
        cudaStreamCreateWithFlags(&sB, cudaStreamNonBlocking);
        cudaEventCreateWithFlags(&evFork, cudaEventDisableTiming);
        cudaEventCreateWithFlags(&evA, cudaEventDisableTiming);
        cudaEventCreateWithFlags(&evB, cudaEventDisableTiming);
    }
};
static StreamPack g_sp;

__device__ __forceinline__ void atomicMaxF(float* addr, float v) {
    if (v >= 0.f) atomicMax((int*)addr, __float_as_int(v));
    else          atomicMin((unsigned int*)addr, __float_as_uint(v));
}

// ---- packed f32x2 helpers (FFMA2 path, sm_103a) ----
__device__ __forceinline__ unsigned long long pack2(float x) {
    unsigned long long r;
    asm("mov.b64 %0, {%1, %2};" : "=l"(r) : "f"(x), "f"(x));
    return r;
}
__device__ __forceinline__ void fma2(unsigned long long& d, unsigned long long a,
                                     unsigned long long b) {
    asm("fma.rn.f32x2 %0, %1, %2, %0;" : "+l"(d) : "l"(a), "l"(b));
}
__device__ __forceinline__ float2 unpack2(unsigned long long v) {
    float lo, hi;
    asm("mov.b64 {%0, %1}, %2;" : "=f"(lo), "=f"(hi) : "l"(v));
    return make_float2(lo, hi);
}

// ---------------- prologue: is64 detect + gmax init + zero g_fill ----------
__global__ void detect_zero_kernel(const int* __restrict__ buf) {
    int t = blockIdx.x * blockDim.x + threadIdx.x;
    if (t < NN) g_fill[t] = 0;
    if (blockIdx.x == 0 && threadIdx.x == 0) {
        int orv = 0;
        #pragma unroll
        for (int i = 1; i < 64; i += 2) orv |= buf[i];
        g_is64 = (orv == 0) ? 1 : 0;
    }
    if (blockIdx.x == 0 && threadIdx.x < 12 && threadIdx.x >= 4)
        ;   // nothing
    if (blockIdx.x == 1 && threadIdx.x < 12) g_gmax[threadIdx.x] = -3.0e38f;
}

// degree count: decode dst directly from the input buffer
__global__ void count_kernel(const int* __restrict__ buf) {
    int t = blockIdx.x * blockDim.x + threadIdx.x;
    if (t >= ETOT) return;
    int d;
    if (t < EE) {
        d = g_is64 ? buf[2 * (EE + t)] : buf[EE + t];
    } else {
        d = t - EE;
    }
    atomicAdd(&g_fill[d], 1);
}

// ---------------- 3-phase coalesced scan ----------------
__global__ void block_sum_kernel() {
    __shared__ int ws[32];
    int tid = threadIdx.x;
    int idx = blockIdx.x * 1024 + tid;
    int v = (idx < NN) ? g_fill[idx] : 0;
    #pragma unroll
    for (int o = 16; o >= 1; o >>= 1) v += __shfl_xor_sync(0xffffffff, v, o);
    int lane = tid & 31, wid = tid >> 5;
    if (lane == 0) ws[wid] = v;
    __syncthreads();
    if (wid == 0) {
        int w = ws[lane];
        #pragma unroll
        for (int o = 16; o >= 1; o >>= 1) w += __shfl_xor_sync(0xffffffff, w, o);
        if (lane == 0) g_bsum[blockIdx.x] = w;
    }
}

__global__ void scan_bsum_kernel() {
    __shared__ int sm[64];
    int tid = threadIdx.x;
    int v = (tid < NBLK) ? g_bsum[tid] : 0;
    sm[tid] = v;
    __syncthreads();
    #pragma unroll
    for (int o = 1; o < 64; o <<= 1) {
        int t2 = (tid >= o) ? sm[tid - o] : 0;
        __syncthreads();
        sm[tid] += t2;
        __syncthreads();
    }
    if (tid < NBLK) g_bsum[tid] = sm[tid] - v;
}

__global__ void rowptr_kernel() {
    __shared__ int ws[32];
    int tid = threadIdx.x;
    int idx = blockIdx.x * 1024 + tid;
    int lane = tid & 31, wid = tid >> 5;
    int c = (idx < NN) ? g_fill[idx] : 0;
    int v = c;
    #pragma unroll
    for (int o = 1; o < 32; o <<= 1) {
        int t2 = __shfl_up_sync(0xffffffff, v, o);
        if (lane >= o) v += t2;
    }
    if (lane == 31) ws[wid] = v;
    __syncthreads();
    if (wid == 0) {
        int w = ws[lane];
        #pragma unroll
        for (int o = 1; o < 32; o <<= 1) {
            int t2 = __shfl_up_sync(0xffffffff, w, o);
            if (lane >= o) w += t2;
        }
        ws[lane] = w;
    }
    __syncthreads();
    int excl = v - c + (wid > 0 ? ws[wid - 1] : 0) + g_bsum[blockIdx.x];
    if (idx < NN) {
        g_rowptr[idx] = excl;
        g_fill[idx] = excl;
    }
    if (idx == 0) g_rowptr[NN] = ETOT;
}

// fill CSR: decode both endpoints directly from the input buffer
__global__ void csr_fill_kernel(const int* __restrict__ buf) {
    int t = blockIdx.x * blockDim.x + threadIdx.x;
    if (t >= ETOT) return;
    int s, d;
    if (t < EE) {
        if (g_is64) {
            s = buf[2 * t];
            d = buf[2 * (EE + t)];
        } else {
            s = buf[t];
            d = buf[EE + t];
        }
    } else {
        s = d = t - EE;
    }
    int pos = atomicAdd(&g_fill[d], 1);
    g_csrc[pos] = s;
}

// ---------------- GEMM (FFMA2) + fused attention logits ----------------
template<int OUT, bool FROMACT>
__global__ __launch_bounds__(128) void gemm_al_kernel(
        const float* __restrict__ X, const float* __restrict__ W,
        const float* __restrict__ a_src, const float* __restrict__ a_dst,
        int gslot) {
    constexpr int NPB = (OUT == 128) ? 64 : 128;
    constexpr int CPT = (OUT == 128) ? 8 : 4;
    constexpr int CP2 = CPT / 2;
    constexpr int CGN = OUT / CPT;
    constexpr int KC  = 32;
    constexpr int NH  = (OUT == 128) ? 4 : 1;

    __shared__ __align__(16) float Xs[KC][NPB];
    __shared__ __align__(16) float Ws[KC][OUT];
    __shared__ float smax[NH];

    const float* __restrict__ Xp = FROMACT ? g_act : X;
    const int tid = threadIdx.x;
    const int cg = tid % CGN;
    const int ng = tid / CGN;
    const int row0 = blockIdx.x * NPB;

    if (tid < NH) smax[tid] = -3.0e38f;

    unsigned long long acc2[8][CP2];
    #pragma unroll
    for (int i = 0; i < 8; i++)
        #pragma unroll
        for (int j = 0; j < CP2; j++) acc2[i][j] = 0ull;

    for (int kc = 0; kc < HC; kc += KC) {
        __syncthreads();
        #pragma unroll
        for (int e = tid; e < KC * NPB / 4; e += 128) {
            int n  = e / (KC / 4);
            int kq = e % (KC / 4);
            int row = row0 + n; if (row >= NN) row = NN - 1;
            float4 v = *(const float4*)&Xp[row * HC + kc + kq * 4];
            Xs[kq * 4 + 0][n] = v.x;
            Xs[kq * 4 + 1][n] = v.y;
            Xs[kq * 4 + 2][n] = v.z;
            Xs[kq * 4 + 3][n] = v.w;
        }
        #pragma unroll
        for (int e = tid; e < KC * OUT / 4; e += 128) {
            ((float4*)&Ws[0][0])[e] = ((const float4*)&W[kc * OUT])[e];
        }
        __syncthreads();

        #pragma unroll
        for (int k = 0; k < KC; k++) {
            float4 xa = *(const float4*)&Xs[k][ng * 8];
            float4 xb = *(const float4*)&Xs[k][ng * 8 + 4];
            unsigned long long xd[8];
            xd[0] = pack2(xa.x); xd[1] = pack2(xa.y);
            xd[2] = pack2(xa.z); xd[3] = pack2(xa.w);
            xd[4] = pack2(xb.x); xd[5] = pack2(xb.y);
            xd[6] = pack2(xb.z); xd[7] = pack2(xb.w);

            unsigned long long wp[CP2];
            {
                double2 w0 = *(const double2*)&Ws[k][cg * CPT];
                wp[0] = __double_as_longlong(w0.x);
                wp[1] = __double_as_longlong(w0.y);
                if (CP2 == 4) {
                    double2 w1 = *(const double2*)&Ws[k][cg * CPT + 4];
                    wp[2] = __double_as_longlong(w1.x);
                    wp[3] = __double_as_longlong(w1.y);
                }
            }
            #pragma unroll
            for (int i = 0; i < 8; i++)
                #pragma unroll
                for (int j = 0; j < CP2; j++)
                    fma2(acc2[i][j], xd[i], wp[j]);
        }
    }

    float acc[8][CPT];
    #pragma unroll
    for (int i = 0; i < 8; i++)
        #pragma unroll
        for (int j = 0; j < CP2; j++) {
            float2 v = unpack2(acc2[i][j]);
            acc[i][2 * j] = v.x;
            acc[i][2 * j + 1] = v.y;
        }

    // store messages as fp16 (half2 pairs)
    #pragma unroll
    for (int i = 0; i < 8; i++) {
        int row = row0 + ng * 8 + i;
        if (row < NN) {
            #pragma unroll
            for (int j = 0; j < CP2; j++) {
                __half2 h = __float22half2_rn(make_float2(acc[i][2 * j], acc[i][2 * j + 1]));
                *(__half2*)&g_lin16[row * OUT + cg * CPT + 2 * j] = h;
            }
        }
    }

    // ---- fused al ----
    float asv[CPT], adv[CPT];
    {
        float4 a0 = *(const float4*)&a_src[cg * CPT];
        asv[0] = a0.x; asv[1] = a0.y; asv[2] = a0.z; asv[3] = a0.w;
        float4 d0 = *(const float4*)&a_dst[cg * CPT];
        adv[0] = d0.x; adv[1] = d0.y; adv[2] = d0.z; adv[3] = d0.w;
        if (CPT == 8) {
            float4 a1 = *(const float4*)&a_src[cg * CPT + 4];
            asv[4] = a1.x; asv[5] = a1.y; asv[6] = a1.z; asv[7] = a1.w;
            float4 d1 = *(const float4*)&a_dst[cg * CPT + 4];
            adv[4] = d1.x; adv[5] = d1.y; adv[6] = d1.z; adv[7] = d1.w;
        }
    }
    float ssp[8], sdp[8];
    #pragma unroll
    for (int i = 0; i < 8; i++) {
        float ss = 0.f, sd = 0.f;
        #pragma unroll
        for (int j = 0; j < CPT; j++) {
            ss += acc[i][j] * asv[j];
            sd += acc[i][j] * adv[j];
        }
        ssp[i] = ss; sdp[i] = sd;
    }
    #pragma unroll
    for (int i = 0; i < 8; i++) {
        ssp[i] += __shfl_xor_sync(0xffffffff, ssp[i], 1);
        sdp[i] += __shfl_xor_sync(0xffffffff, sdp[i], 1);
        ssp[i] += __shfl_xor_sync(0xffffffff, ssp[i], 2);
        sdp[i] += __shfl_xor_sync(0xffffffff, sdp[i], 2);
        if (OUT == 32) {
            ssp[i] += __shfl_xor_sync(0xffffffff, ssp[i], 4);
            sdp[i] += __shfl_xor_sync(0xffffffff, sdp[i], 4);
        }
    }
    float lmax = -3.0e38f;
    if (OUT == 128) {
        if ((cg & 3) == 0) {
            int h = cg >> 2;
            #pragma unroll
            for (int i = 0; i < 8; i++) {
                int row = row0 + ng * 8 + i;
                if (row < NN) {
                    g_alsrc[row * HH + h] = ssp[i];
                    g_aldst[row * HH + h] = sdp[i];
                    lmax = fmaxf(lmax, ssp[i]);
                }
            }
            atomicMaxF(&smax[h], lmax);
        }
    } else {
        if (cg == 0) {
            #pragma unroll
            for (int i = 0; i < 8; i++) {
                int row = row0 + ng * 8 + i;
                if (row < NN) {
                    g_alsrc[row] = ssp[i];
                    g_aldst[row] = sdp[i];
                    lmax = fmaxf(lmax, ssp[i]);
                }
            }
            atomicMaxF(&smax[0], lmax);
        }
    }
    __syncthreads();
    if (tid < NH) atomicMaxF(&g_gmax[gslot + tid], smax[tid]);
}

// ---------------- single-pass fused GAT aggregation (warp per dst, fp16 gather) --
__global__ __launch_bounds__(256) void gat_agg4_kernel(const float* __restrict__ b,
                                                       int gslot, int do_elu) {
    __shared__ int    ss[8][32];
    __shared__ float4 ww[8][32];

    int warp = (blockIdx.x * blockDim.x + threadIdx.x) >> 5;
    if (warp >= NN) return;
    int lane = threadIdx.x & 31;
    int wslot = (threadIdx.x >> 5) & 7;
    int d = warp;
    int start = g_rowptr[d], end = g_rowptr[d + 1];

    float4 ad = *(const float4*)&g_aldst[d * HH];
    float4 gm = *(const float4*)&g_gmax[gslot];
    float4 m;
    m.x = gm.x + ad.x; m.x = (m.x > 0.f) ? m.x : 0.2f * m.x;
    m.y = gm.y + ad.y; m.y = (m.y > 0.f) ? m.y : 0.2f * m.y;
    m.z = gm.z + ad.z; m.z = (m.z > 0.f) ? m.z : 0.2f * m.z;
    m.w = gm.w + ad.w; m.w = (m.w > 0.f) ? m.w : 0.2f * m.w;

    const int h0 = lane >> 4;
    const int h1 = 2 + h0;

    float4 denom = make_float4(0.f, 0.f, 0.f, 0.f);
    float a0x = 0.f, a0y = 0.f, a1x = 0.f, a1y = 0.f;

    for (int base = start; base < end; base += 32) {
        int i = base + lane;
        float4 w = make_float4(0.f, 0.f, 0.f, 0.f);
        int s = 0;
        if (i < end) {
            s = g_csrc[i];
            float4 v = *(const float4*)&g_alsrc[s * HH];
            v.x += ad.x; v.y += ad.y; v.z += ad.z; v.w += ad.w;
            v.x = (v.x > 0.f) ? v.x : 0.2f * v.x;
            v.y = (v.y > 0.f) ? v.y : 0.2f * v.y;
            v.z = (v.z > 0.f) ? v.z : 0.2f * v.z;
            v.w = (v.w > 0.f) ? v.w : 0.2f * v.w;
            w.x = __expf(v.x - m.x);
            w.y = __expf(v.y - m.y);
            w.z = __expf(v.z - m.z);
            w.w = __expf(v.w - m.w);
        }
        denom.x += w.x; denom.y += w.y; denom.z += w.z; denom.w += w.w;
        ss[wslot][lane] = s;
        ww[wslot][lane] = w;
        __syncwarp();
        int n = min(32, end - base);
        for (int j = 0; j < n; j++) {
            int sj = ss[wslot][j];
            const float* wjp = (const float*)&ww[wslot][j];
            float w0 = wjp[h0];
            float w1 = wjp[h1];
            const __half2* hp = (const __half2*)(g_lin16 + sj * HC);
            float2 m0 = __half22float2(hp[lane]);
            float2 m1 = __half22float2(hp[32 + lane]);
            a0x += w0 * m0.x; a0y += w0 * m0.y;
            a1x += w1 * m1.x; a1y += w1 * m1.y;
        }
        __syncwarp();
    }

    #pragma unroll
    for (int o = 16; o >= 1; o >>= 1) {
        denom.x += __shfl_xor_sync(0xffffffff, denom.x, o);
        denom.y += __shfl_xor_sync(0xffffffff, denom.y, o);
        denom.z += __shfl_xor_sync(0xffffffff, denom.z, o);
        denom.w += __shfl_xor_sync(0xffffffff, denom.w, o);
    }
    float rd0 = 1.f / ((h0 == 0 ? denom.x : denom.y) + 1e-16f);
    float rd1 = 1.f / ((h1 == 2 ? denom.z : denom.w) + 1e-16f);

    float2 b0 = *(const float2*)&b[2 * lane];
    float2 b1 = *(const float2*)&b[64 + 2 * lane];
    a0x = a0x * rd0 + b0.x;
    a0y = a0y * rd0 + b0.y;
    a1x = a1x * rd1 + b1.x;
    a1y = a1y * rd1 + b1.y;
    if (do_elu) {
        a0x = (a0x > 0.f) ? a0x : (__expf(a0x) - 1.f);
        a0y = (a0y > 0.f) ? a0y : (__expf(a0y) - 1.f);
        a1x = (a1x > 0.f) ? a1x : (__expf(a1x) - 1.f);
        a1y = (a1y > 0.f) ? a1y : (__expf(a1y) - 1.f);
    }
    float* o = g_act + d * HC;
    *(float2*)&o[2 * lane] = make_float2(a0x, a0y);
    *(float2*)&o[64 + 2 * lane] = make_float2(a1x, a1y);
}

// layer 3 (H=1) fused with classifier head + embedding write
__global__ __launch_bounds__(256) void gat_agg1_head_kernel(
        const float* __restrict__ b, const float* __restrict__ Wc,
        const float* __restrict__ bc, float* __restrict__ out) {
    __shared__ int   ss[8][32];
    __shared__ float ww[8][32];

    int warp = (blockIdx.x * blockDim.x + threadIdx.x) >> 5;
    if (warp >= NN) return;
    int lane = threadIdx.x & 31;
    int wslot = (threadIdx.x >> 5) & 7;
    int d = warp;
    int start = g_rowptr[d], end = g_rowptr[d + 1];

    float ad = g_aldst[d];
    float gm = g_gmax[8];
    float m = gm + ad; m = (m > 0.f) ? m : 0.2f * m;

    float denom = 0.f;
    float acc = 0.f;

    for (int base = start; base < end; base += 32) {
        int i = base + lane;
        float w = 0.f;
        int s = 0;
        if (i < end) {
            s = g_csrc[i];
            float v = g_alsrc[s] + ad;
            v = (v > 0.f) ? v : 0.2f * v;
            w = __expf(v - m);
        }
        denom += w;
        ss[wslot][lane] = s;
        ww[wslot][lane] = w;
        __syncwarp();
        int n = min(32, end - base);
        for (int j = 0; j < n; j++) {
            acc += ww[wslot][j] * __half2float(g_lin16[ss[wslot][j] * CC + lane]);
        }
        __syncwarp();
    }
    #pragma unroll
    for (int o = 16; o >= 1; o >>= 1)
        denom += __shfl_xor_sync(0xffffffff, denom, o);

    float h = acc / (denom + 1e-16f) + b[lane];

    out[NN * 2 + d * CC + lane] = h;

    float o0 = h * Wc[lane * 2 + 0];
    float o1 = h * Wc[lane * 2 + 1];
    #pragma unroll
    for (int o = 16; o >= 1; o >>= 1) {
        o0 += __shfl_xor_sync(0xffffffff, o0, o);
        o1 += __shfl_xor_sync(0xffffffff, o1, o);
    }
    if (lane == 0) {
        out[d * 2 + 0] = o0 + bc[0];
        out[d * 2 + 1] = o1 + bc[1];
    }
}

// ---------------- launch ----------------
extern "C" void kernel_launch(void* const* d_in, const int* in_sizes, int n_in,
                              void* d_out, int out_size) {
    const float* x   = (const float*)d_in[0];
    const int*   ei  = (const int*)d_in[1];
    const float* W1  = (const float*)d_in[2];
    const float* a1s = (const float*)d_in[3];
    const float* a1d = (const float*)d_in[4];
    const float* b1  = (const float*)d_in[5];
    const float* W2  = (const float*)d_in[6];
    const float* a2s = (const float*)d_in[7];
    const float* a2d = (const float*)d_in[8];
    const float* b2  = (const float*)d_in[9];
    const float* W3  = (const float*)d_in[10];
    const float* a3s = (const float*)d_in[11];
    const float* a3d = (const float*)d_in[12];
    const float* b3  = (const float*)d_in[13];
    const float* Wc  = (const float*)d_in[14];
    const float* bc  = (const float*)d_in[15];
    float* out = (float*)d_out;

    const int T = 256;
    const int gE = (ETOT + T - 1) / T;
    const int gN = (NN + T - 1) / T;
    const int gW = (NN * 32 + T - 1) / T;

    cudaStream_t s0 = 0;                // capture-origin stream
    cudaStream_t sA = g_sp.sA;          // CSR branch
    cudaStream_t sB = g_sp.sB;          // GEMM1 branch

    // shared prologue: is64 detect + gmax init + zero g_fill (one launch)
    detect_zero_kernel<<<gN, T, 0, s0>>>(ei);

    // fork
    cudaEventRecord(g_sp.evFork, s0);
    cudaStreamWaitEvent(sA, g_sp.evFork, 0);
    cudaStreamWaitEvent(sB, g_sp.evFork, 0);

    // ---- branch A: CSR build ----
    count_kernel<<<gE, T, 0, sA>>>(ei);
    block_sum_kernel<<<NBLK, 1024, 0, sA>>>();
    scan_bsum_kernel<<<1, 64, 0, sA>>>();
    rowptr_kernel<<<NBLK, 1024, 0, sA>>>();
    csr_fill_kernel<<<gE, T, 0, sA>>>(ei);
    cudaEventRecord(g_sp.evA, sA);

    // ---- branch B: layer-1 GEMM + attention logits ----
    gemm_al_kernel<128, false><<<(NN + 63) / 64, 128, 0, sB>>>(x, W1, a1s, a1d, 0);
    cudaEventRecord(g_sp.evB, sB);

    // join on the capture stream
    cudaStreamWaitEvent(s0, g_sp.evA, 0);
    cudaStreamWaitEvent(s0, g_sp.evB, 0);

    // ---- serial layer chain (R8 schedule) ----
    gat_agg4_kernel<<<gW, T, 0, s0>>>(b1, 0, 1);
    gemm_al_kernel<128, true><<<(NN + 63) / 64, 128, 0, s0>>>(nullptr, W2, a2s, a2d, 4);
    gat_agg4_kernel<<<gW, T, 0, s0>>>(b2, 4, 1);
    gemm_al_kernel<32, true><<<(NN + 127) / 128, 128, 0, s0>>>(nullptr, W3, a3s, a3d, 8);
    gat_agg1_head_kernel<<<gW, T, 0, s0>>>(b3, Wc, bc, out);
}

// round 14
// speedup vs baseline: 1.3830x; 1.0370x over previous
#include <cuda_runtime.h>
#include <cuda_fp16.h>

// Problem constants (fixed by the dataset)
#define NN 50000
#define EE 800000
#define ETOT 850000   // EE + NN self-loops
#define HH 4
#define CC 32
#define HC 128        // HH*CC
#define NBLK ((NN + 1023) / 1024)   // 49 scan blocks
#define EE2 (EE / 2)                // 400000 edge pairs

// ---------------- scratch (device globals: allocation-free) ----------------
__device__ __align__(16) __half g_lin16[NN * HC];  // messages (fp16, gather-only)
__device__ float g_act[NN * HC];
__device__ float g_alsrc[NN * HH];
__device__ float g_aldst[NN * HH];
__device__ __align__(16) float g_gmax[12];
__device__ int   g_csrc[ETOT];
__device__ int   g_rowptr[NN + 1];
__device__ int   g_fill[NN];
__device__ int   g_bsum[64];
__device__ int   g_is64;

// ---------------- streams for fork/join inside graph capture --------------
struct StreamPack {
    cudaStream_t sA, sB;
    cudaEvent_t evFork, evA, evB;
    StreamPack() {
        cudaStreamCreateWithFlags(&sA, cudaStreamNonBlocking);
        cudaStreamCreateWithFlags(&sB, cudaStreamNonBlocking);
        cudaEventCreateWithFlags(&evFork, cudaEventDisableTiming);
        cudaEventCreateWithFlags(&evA, cudaEventDisableTiming);
        cudaEventCreateWithFlags(&evB, cudaEventDisableTiming);
    }
};
static StreamPack g_sp;

__device__ __forceinline__ void atomicMaxF(float* addr, float v) {
    if (v >= 0.f) atomicMax((int*)addr, __float_as_int(v));
    else          atomicMin((unsigned int*)addr, __float_as_uint(v));
}

// ---- packed f32x2 helpers (FFMA2 path, sm_103a) ----
__device__ __forceinline__ unsigned long long pack2(float x) {
    unsigned long long r;
    asm("mov.b64 %0, {%1, %2};" : "=l"(r) : "f"(x), "f"(x));
    return r;
}
__device__ __forceinline__ void fma2(unsigned long long& d, unsigned long long a,
                                     unsigned long long b) {
    asm("fma.rn.f32x2 %0, %1, %2, %0;" : "+l"(d) : "l"(a), "l"(b));
}
__device__ __forceinline__ float2 unpack2(unsigned long long v) {
    float lo, hi;
    asm("mov.b64 {%0, %1}, %2;" : "=f"(lo), "=f"(hi) : "l"(v));
    return make_float2(lo, hi);
}

// ---------------- prologue: is64 detect + gmax init + g_fill = 1 ----------
// g_fill starts at 1: accounts for every node's self-loop (count skips them).
__global__ void detect_zero_kernel(const int* __restrict__ buf) {
    int t = blockIdx.x * blockDim.x + threadIdx.x;
    if (t < NN) g_fill[t] = 1;
    if (blockIdx.x == 0 && threadIdx.x == 0) {
        int orv = 0;
        #pragma unroll
        for (int i = 1; i < 64; i += 2) orv |= buf[i];
        g_is64 = (orv == 0) ? 1 : 0;
    }
    if (blockIdx.x == 1 && threadIdx.x < 12) g_gmax[threadIdx.x] = -3.0e38f;
}

// degree count: 2 edges per thread, vectorized dst decode
__global__ void count_kernel(const int* __restrict__ buf) {
    int u = blockIdx.x * blockDim.x + threadIdx.x;
    if (u >= EE2) return;
    int d0, d1;
    if (g_is64) {
        int4 v = ((const int4*)buf)[EE2 + u];   // int64 dst pair @ int32 offset 2EE+4u
        d0 = v.x; d1 = v.z;
    } else {
        int2 v = ((const int2*)(buf + EE))[u];
        d0 = v.x; d1 = v.y;
    }
    atomicAdd(&g_fill[d0], 1);
    atomicAdd(&g_fill[d1], 1);
}

// ---------------- 2-phase coalesced scan (bsum prefix folded into rowptr) ----
__global__ void block_sum_kernel() {
    __shared__ int ws[32];
    int tid = threadIdx.x;
    int idx = blockIdx.x * 1024 + tid;
    int v = (idx < NN) ? g_fill[idx] : 0;
    #pragma unroll
    for (int o = 16; o >= 1; o >>= 1) v += __shfl_xor_sync(0xffffffff, v, o);
    int lane = tid & 31, wid = tid >> 5;
    if (lane == 0) ws[wid] = v;
    __syncthreads();
    if (wid == 0) {
        int w = ws[lane];
        #pragma unroll
        for (int o = 16; o >= 1; o >>= 1) w += __shfl_xor_sync(0xffffffff, w, o);
        if (lane == 0) g_bsum[blockIdx.x] = w;
    }
}

__global__ void rowptr_kernel() {
    __shared__ int ws[32];
    __shared__ int bofs;
    int tid = threadIdx.x;
    int idx = blockIdx.x * 1024 + tid;
    int lane = tid & 31, wid = tid >> 5;

    // warp 0: exclusive prefix of g_bsum up to this block (2 elems per lane)
    if (wid == 0) {
        int B = blockIdx.x;
        int a = (lane < B) ? g_bsum[lane] : 0;
        int b2 = (lane + 32 < B) ? g_bsum[lane + 32] : 0;
        int v = a + b2;
        #pragma unroll
        for (int o = 16; o >= 1; o >>= 1) v += __shfl_xor_sync(0xffffffff, v, o);
        if (lane == 0) bofs = v;
    }

    int c = (idx < NN) ? g_fill[idx] : 0;
    int v = c;
    #pragma unroll
    for (int o = 1; o < 32; o <<= 1) {
        int t2 = __shfl_up_sync(0xffffffff, v, o);
        if (lane >= o) v += t2;
    }
    if (lane == 31) ws[wid] = v;
    __syncthreads();
    if (wid == 0) {
        int w = ws[lane];
        #pragma unroll
        for (int o = 1; o < 32; o <<= 1) {
            int t2 = __shfl_up_sync(0xffffffff, w, o);
            if (lane >= o) w += t2;
        }
        ws[lane] = w;
    }
    __syncthreads();
    int excl = v - c + (wid > 0 ? ws[wid - 1] : 0) + bofs;
    if (idx < NN) {
        g_rowptr[idx] = excl;
        g_fill[idx] = excl;
    }
    if (idx == 0) g_rowptr[NN] = ETOT;
}

// fill CSR: 2 edges per thread, vectorized decode; self-loops in the tail
__global__ void csr_fill_kernel(const int* __restrict__ buf) {
    int u = blockIdx.x * blockDim.x + threadIdx.x;
    if (u < EE2) {
        int s0, s1, d0, d1;
        if (g_is64) {
            int4 sv = ((const int4*)buf)[u];          // src pair @ int32 offset 4u
            int4 dv = ((const int4*)buf)[EE2 + u];
            s0 = sv.x; s1 = sv.z; d0 = dv.x; d1 = dv.z;
        } else {
            int2 sv = ((const int2*)buf)[u];
            int2 dv = ((const int2*)(buf + EE))[u];
            s0 = sv.x; s1 = sv.y; d0 = dv.x; d1 = dv.y;
        }
        g_csrc[atomicAdd(&g_fill[d0], 1)] = s0;
        g_csrc[atomicAdd(&g_fill[d1], 1)] = s1;
    } else {
        int v = u - EE2;
        if (v < NN) g_csrc[atomicAdd(&g_fill[v], 1)] = v;   // self-loop
    }
}

// ---------------- GEMM (FFMA2) + fused attention logits ----------------
template<int OUT, bool FROMACT>
__global__ __launch_bounds__(128) void gemm_al_kernel(
        const float* __restrict__ X, const float* __restrict__ W,
        const float* __restrict__ a_src, const float* __restrict__ a_dst,
        int gslot) {
    constexpr int NPB = (OUT == 128) ? 64 : 128;
    constexpr int CPT = (OUT == 128) ? 8 : 4;
    constexpr int CP2 = CPT / 2;
    constexpr int CGN = OUT / CPT;
    constexpr int KC  = 32;
    constexpr int NH  = (OUT == 128) ? 4 : 1;

    __shared__ __align__(16) float Xs[KC][NPB];
    __shared__ __align__(16) float Ws[KC][OUT];
    __shared__ float smax[NH];

    const float* __restrict__ Xp = FROMACT ? g_act : X;
    const int tid = threadIdx.x;
    const int cg = tid % CGN;
    const int ng = tid / CGN;
    const int row0 = blockIdx.x * NPB;

    if (tid < NH) smax[tid] = -3.0e38f;

    unsigned long long acc2[8][CP2];
    #pragma unroll
    for (int i = 0; i < 8; i++)
        #pragma unroll
        for (int j = 0; j < CP2; j++) acc2[i][j] = 0ull;

    for (int kc = 0; kc < HC; kc += KC) {
        __syncthreads();
        #pragma unroll
        for (int e = tid; e < KC * NPB / 4; e += 128) {
            int n  = e / (KC / 4);
            int kq = e % (KC / 4);
            int row = row0 + n; if (row >= NN) row = NN - 1;
            float4 v = *(const float4*)&Xp[row * HC + kc + kq * 4];
            Xs[kq * 4 + 0][n] = v.x;
            Xs[kq * 4 + 1][n] = v.y;
            Xs[kq * 4 + 2][n] = v.z;
            Xs[kq * 4 + 3][n] = v.w;
        }
        #pragma unroll
        for (int e = tid; e < KC * OUT / 4; e += 128) {
            ((float4*)&Ws[0][0])[e] = ((const float4*)&W[kc * OUT])[e];
        }
        __syncthreads();

        #pragma unroll
        for (int k = 0; k < KC; k++) {
            float4 xa = *(const float4*)&Xs[k][ng * 8];
            float4 xb = *(const float4*)&Xs[k][ng * 8 + 4];
            unsigned long long xd[8];
            xd[0] = pack2(xa.x); xd[1] = pack2(xa.y);
            xd[2] = pack2(xa.z); xd[3] = pack2(xa.w);
            xd[4] = pack2(xb.x); xd[5] = pack2(xb.y);
            xd[6] = pack2(xb.z); xd[7] = pack2(xb.w);

            unsigned long long wp[CP2];
            {
                double2 w0 = *(const double2*)&Ws[k][cg * CPT];
                wp[0] = __double_as_longlong(w0.x);
                wp[1] = __double_as_longlong(w0.y);
                if (CP2 == 4) {
                    double2 w1 = *(const double2*)&Ws[k][cg * CPT + 4];
                    wp[2] = __double_as_longlong(w1.x);
                    wp[3] = __double_as_longlong(w1.y);
                }
            }
            #pragma unroll
            for (int i = 0; i < 8; i++)
                #pragma unroll
                for (int j = 0; j < CP2; j++)
                    fma2(acc2[i][j], xd[i], wp[j]);
        }
    }

    float acc[8][CPT];
    #pragma unroll
    for (int i = 0; i < 8; i++)
        #pragma unroll
        for (int j = 0; j < CP2; j++) {
            float2 v = unpack2(acc2[i][j]);
            acc[i][2 * j] = v.x;
            acc[i][2 * j + 1] = v.y;
        }

    // store messages as fp16 (half2 pairs)
    #pragma unroll
    for (int i = 0; i < 8; i++) {
        int row = row0 + ng * 8 + i;
        if (row < NN) {
            #pragma unroll
            for (int j = 0; j < CP2; j++) {
                __half2 h = __float22half2_rn(make_float2(acc[i][2 * j], acc[i][2 * j + 1]));
                *(__half2*)&g_lin16[row * OUT + cg * CPT + 2 * j] = h;
            }
        }
    }

    // ---- fused al ----
    float asv[CPT], adv[CPT];
    {
        float4 a0 = *(const float4*)&a_src[cg * CPT];
        asv[0] = a0.x; asv[1] = a0.y; asv[2] = a0.z; asv[3] = a0.w;
        float4 d0 = *(const float4*)&a_dst[cg * CPT];
        adv[0] = d0.x; adv[1] = d0.y; adv[2] = d0.z; adv[3] = d0.w;
        if (CPT == 8) {
            float4 a1 = *(const float4*)&a_src[cg * CPT + 4];
            asv[4] = a1.x; asv[5] = a1.y; asv[6] = a1.z; asv[7] = a1.w;
            float4 d1 = *(const float4*)&a_dst[cg * CPT + 4];
            adv[4] = d1.x; adv[5] = d1.y; adv[6] = d1.z; adv[7] = d1.w;
        }
    }
    float ssp[8], sdp[8];
    #pragma unroll
    for (int i = 0; i < 8; i++) {
        float ss = 0.f, sd = 0.f;
        #pragma unroll
        for (int j = 0; j < CPT; j++) {
            ss += acc[i][j] * asv[j];
            sd += acc[i][j] * adv[j];
        }
        ssp[i] = ss; sdp[i] = sd;
    }
    #pragma unroll
    for (int i = 0; i < 8; i++) {
        ssp[i] += __shfl_xor_sync(0xffffffff, ssp[i], 1);
        sdp[i] += __shfl_xor_sync(0xffffffff, sdp[i], 1);
        ssp[i] += __shfl_xor_sync(0xffffffff, ssp[i], 2);
        sdp[i] += __shfl_xor_sync(0xffffffff, sdp[i], 2);
        if (OUT == 32) {
            ssp[i] += __shfl_xor_sync(0xffffffff, ssp[i], 4);
            sdp[i] += __shfl_xor_sync(0xffffffff, sdp[i], 4);
        }
    }
    float lmax = -3.0e38f;
    if (OUT == 128) {
        if ((cg & 3) == 0) {
            int h = cg >> 2;
            #pragma unroll
            for (int i = 0; i < 8; i++) {
                int row = row0 + ng * 8 + i;
                if (row < NN) {
                    g_alsrc[row * HH + h] = ssp[i];
                    g_aldst[row * HH + h] = sdp[i];
                    lmax = fmaxf(lmax, ssp[i]);
                }
            }
            atomicMaxF(&smax[h], lmax);
        }
    } else {
        if (cg == 0) {
            #pragma unroll
            for (int i = 0; i < 8; i++) {
                int row = row0 + ng * 8 + i;
                if (row < NN) {
                    g_alsrc[row] = ssp[i];
                    g_aldst[row] = sdp[i];
                    lmax = fmaxf(lmax, ssp[i]);
                }
            }
            atomicMaxF(&smax[0], lmax);
        }
    }
    __syncthreads();
    if (tid < NH) atomicMaxF(&g_gmax[gslot + tid], smax[tid]);
}

// ---------------- single-pass fused GAT aggregation (warp per dst, fp16 gather) --
__global__ __launch_bounds__(256) void gat_agg4_kernel(const float* __restrict__ b,
                                                       int gslot, int do_elu) {
    __shared__ int    ss[8][32];
    __shared__ float4 ww[8][32];

    int warp = (blockIdx.x * blockDim.x + threadIdx.x) >> 5;
    if (warp >= NN) return;
    int lane = threadIdx.x & 31;
    int wslot = (threadIdx.x >> 5) & 7;
    int d = warp;
    int start = g_rowptr[d], end = g_rowptr[d + 1];

    float4 ad = *(const float4*)&g_aldst[d * HH];
    float4 gm = *(const float4*)&g_gmax[gslot];
    float4 m;
    m.x = gm.x + ad.x; m.x = (m.x > 0.f) ? m.x : 0.2f * m.x;
    m.y = gm.y + ad.y; m.y = (m.y > 0.f) ? m.y : 0.2f * m.y;
    m.z = gm.z + ad.z; m.z = (m.z > 0.f) ? m.z : 0.2f * m.z;
    m.w = gm.w + ad.w; m.w = (m.w > 0.f) ? m.w : 0.2f * m.w;

    const int h0 = lane >> 4;
    const int h1 = 2 + h0;

    float4 denom = make_float4(0.f, 0.f, 0.f, 0.f);
    float a0x = 0.f, a0y = 0.f, a1x = 0.f, a1y = 0.f;

    for (int base = start; base < end; base += 32) {
        int i = base + lane;
        float4 w = make_float4(0.f, 0.f, 0.f, 0.f);
        int s = 0;
        if (i < end) {
            s = g_csrc[i];
            float4 v = *(const float4*)&g_alsrc[s * HH];
            v.x += ad.x; v.y += ad.y; v.z += ad.z; v.w += ad.w;
            v.x = (v.x > 0.f) ? v.x : 0.2f * v.x;
            v.y = (v.y > 0.f) ? v.y : 0.2f * v.y;
            v.z = (v.z > 0.f) ? v.z : 0.2f * v.z;
            v.w = (v.w > 0.f) ? v.w : 0.2f * v.w;
            w.x = __expf(v.x - m.x);
            w.y = __expf(v.y - m.y);
            w.z = __expf(v.z - m.z);
            w.w = __expf(v.w - m.w);
        }
        denom.x += w.x; denom.y += w.y; denom.z += w.z; denom.w += w.w;
        ss[wslot][lane] = s;
        ww[wslot][lane] = w;
        __syncwarp();
        int n = min(32, end - base);
        int j = 0;
        // unroll by 2: two independent edge gathers in flight
        for (; j + 1 < n; j += 2) {
            int sj0 = ss[wslot][j];
            int sj1 = ss[wslot][j + 1];
            const float* wjp0 = (const float*)&ww[wslot][j];
            const float* wjp1 = (const float*)&ww[wslot][j + 1];
            const __half2* hp0 = (const __half2*)(g_lin16 + sj0 * HC);
            const __half2* hp1 = (const __half2*)(g_lin16 + sj1 * HC);
            float2 p0 = __half22float2(hp0[lane]);
            float2 p1 = __half22float2(hp0[32 + lane]);
            float2 q0 = __half22float2(hp1[lane]);
            float2 q1 = __half22float2(hp1[32 + lane]);
            float w00 = wjp0[h0], w01 = wjp0[h1];
            float w10 = wjp1[h0], w11 = wjp1[h1];
            a0x += w00 * p0.x; a0y += w00 * p0.y;
            a1x += w01 * p1.x; a1y += w01 * p1.y;
            a0x += w10 * q0.x; a0y += w10 * q0.y;
            a1x += w11 * q1.x; a1y += w11 * q1.y;
        }
        if (j < n) {
            int sj = ss[wslot][j];
            const float* wjp = (const float*)&ww[wslot][j];
            const __half2* hp = (const __half2*)(g_lin16 + sj * HC);
            float2 m0 = __half22float2(hp[lane]);
            float2 m1 = __half22float2(hp[32 + lane]);
            float w0 = wjp[h0], w1 = wjp[h1];
            a0x += w0 * m0.x; a0y += w0 * m0.y;
            a1x += w1 * m1.x; a1y += w1 * m1.y;
        }
        __syncwarp();
    }

    #pragma unroll
    for (int o = 16; o >= 1; o >>= 1) {
        denom.x += __shfl_xor_sync(0xffffffff, denom.x, o);
        denom.y += __shfl_xor_sync(0xffffffff, denom.y, o);
        denom.z += __shfl_xor_sync(0xffffffff, denom.z, o);
        denom.w += __shfl_xor_sync(0xffffffff, denom.w, o);
    }
    float rd0 = 1.f / ((h0 == 0 ? denom.x : denom.y) + 1e-16f);
    float rd1 = 1.f / ((h1 == 2 ? denom.z : denom.w) + 1e-16f);

    float2 b0 = *(const float2*)&b[2 * lane];
    float2 b1 = *(const float2*)&b[64 + 2 * lane];
    a0x = a0x * rd0 + b0.x;
    a0y = a0y * rd0 + b0.y;
    a1x = a1x * rd1 + b1.x;
    a1y = a1y * rd1 + b1.y;
    if (do_elu) {
        a0x = (a0x > 0.f) ? a0x : (__expf(a0x) - 1.f);
        a0y = (a0y > 0.f) ? a0y : (__expf(a0y) - 1.f);
        a1x = (a1x > 0.f) ? a1x : (__expf(a1x) - 1.f);
        a1y = (a1y > 0.f) ? a1y : (__expf(a1y) - 1.f);
    }
    float* o = g_act + d * HC;
    *(float2*)&o[2 * lane] = make_float2(a0x, a0y);
    *(float2*)&o[64 + 2 * lane] = make_float2(a1x, a1y);
}

// layer 3 (H=1) fused with classifier head + embedding write
__global__ __launch_bounds__(256) void gat_agg1_head_kernel(
        const float* __restrict__ b, const float* __restrict__ Wc,
        const float* __restrict__ bc, float* __restrict__ out) {
    __shared__ int   ss[8][32];
    __shared__ float ww[8][32];

    int warp = (blockIdx.x * blockDim.x + threadIdx.x) >> 5;
    if (warp >= NN) return;
    int lane = threadIdx.x & 31;
    int wslot = (threadIdx.x >> 5) & 7;
    int d = warp;
    int start = g_rowptr[d], end = g_rowptr[d + 1];

    float ad = g_aldst[d];
    float gm = g_gmax[8];
    float m = gm + ad; m = (m > 0.f) ? m : 0.2f * m;

    float denom = 0.f;
    float acc = 0.f;

    for (int base = start; base < end; base += 32) {
        int i = base + lane;
        float w = 0.f;
        int s = 0;
        if (i < end) {
            s = g_csrc[i];
            float v = g_alsrc[s] + ad;
            v = (v > 0.f) ? v : 0.2f * v;
            w = __expf(v - m);
        }
        denom += w;
        ss[wslot][lane] = s;
        ww[wslot][lane] = w;
        __syncwarp();
        int n = min(32, end - base);
        int j = 0;
        for (; j + 1 < n; j += 2) {
            float v0 = __half2float(g_lin16[ss[wslot][j] * CC + lane]);
            float v1 = __half2float(g_lin16[ss[wslot][j + 1] * CC + lane]);
            acc += ww[wslot][j] * v0 + ww[wslot][j + 1] * v1;
        }
        if (j < n) {
            acc += ww[wslot][j] * __half2float(g_lin16[ss[wslot][j] * CC + lane]);
        }
        __syncwarp();
    }
    #pragma unroll
    for (int o = 16; o >= 1; o >>= 1)
        denom += __shfl_xor_sync(0xffffffff, denom, o);

    float h = acc / (denom + 1e-16f) + b[lane];

    out[NN * 2 + d * CC + lane] = h;

    float o0 = h * Wc[lane * 2 + 0];
    float o1 = h * Wc[lane * 2 + 1];
    #pragma unroll
    for (int o = 16; o >= 1; o >>= 1) {
        o0 += __shfl_xor_sync(0xffffffff, o0, o);
        o1 += __shfl_xor_sync(0xffffffff, o1, o);
    }
    if (lane == 0) {
        out[d * 2 + 0] = o0 + bc[0];
        out[d * 2 + 1] = o1 + bc[1];
    }
}

// ---------------- launch ----------------
extern "C" void kernel_launch(void* const* d_in, const int* in_sizes, int n_in,
                              void* d_out, int out_size) {
    const float* x   = (const float*)d_in[0];
    const int*   ei  = (const int*)d_in[1];
    const float* W1  = (const float*)d_in[2];
    const float* a1s = (const float*)d_in[3];
    const float* a1d = (const float*)d_in[4];
    const float* b1  = (const float*)d_in[5];
    const float* W2  = (const float*)d_in[6];
    const float* a2s = (const float*)d_in[7];
    const float* a2d = (const float*)d_in[8];
    const float* b2  = (const float*)d_in[9];
    const float* W3  = (const float*)d_in[10];
    const float* a3s = (const float*)d_in[11];
    const float* a3d = (const float*)d_in[12];
    const float* b3  = (const float*)d_in[13];
    const float* Wc  = (const float*)d_in[14];
    const float* bc  = (const float*)d_in[15];
    float* out = (float*)d_out;

    const int T = 256;
    const int gN = (NN + T - 1) / T;
    const int gW = (NN * 32 + T - 1) / T;
    const int gC = (EE2 + T - 1) / T;           // count: 2 edges/thread
    const int gF = (EE2 + NN + T - 1) / T;      // fill: pairs + self-loops

    cudaStream_t s0 = 0;                // capture-origin stream
    cudaStream_t sA = g_sp.sA;          // CSR branch
    cudaStream_t sB = g_sp.sB;          // GEMM1 branch

    // shared prologue: is64 detect + gmax init + g_fill = 1 (one launch)
    detect_zero_kernel<<<gN, T, 0, s0>>>(ei);

    // fork
    cudaEventRecord(g_sp.evFork, s0);
    cudaStreamWaitEvent(sA, g_sp.evFork, 0);
    cudaStreamWaitEvent(sB, g_sp.evFork, 0);

    // ---- branch A: CSR build (4 kernels) ----
    count_kernel<<<gC, T, 0, sA>>>(ei);
    block_sum_kernel<<<NBLK, 1024, 0, sA>>>();
    rowptr_kernel<<<NBLK, 1024, 0, sA>>>();
    csr_fill_kernel<<<gF, T, 0, sA>>>(ei);
    cudaEventRecord(g_sp.evA, sA);

    // ---- branch B: layer-1 GEMM + attention logits ----
    gemm_al_kernel<128, false><<<(NN + 63) / 64, 128, 0, sB>>>(x, W1, a1s, a1d, 0);
    cudaEventRecord(g_sp.evB, sB);

    // join on the capture stream
    cudaStreamWaitEvent(s0, g_sp.evA, 0);
    cudaStreamWaitEvent(s0, g_sp.evB, 0);

    // ---- serial layer chain ----
    gat_agg4_kernel<<<gW, T, 0, s0>>>(b1, 0, 1);
    gemm_al_kernel<128, true><<<(NN + 63) / 64, 128, 0, s0>>>(nullptr, W2, a2s, a2d, 4);
    gat_agg4_kernel<<<gW, T, 0, s0>>>(b2, 4, 1);
    gemm_al_kernel<32, true><<<(NN + 127) / 128, 128, 0, s0>>>(nullptr, W3, a3s, a3d, 8);
    gat_agg1_head_kernel<<<gW, T, 0, s0>>>(b3, Wc, bc, out);
}

// round 15
// speedup vs baseline: 1.4240x; 1.0296x over previous
#include <cuda_runtime.h>
#include <cuda_fp16.h>

// Problem constants (fixed by the dataset)
#define NN 50000
#define EE 800000
#define ETOT 850000   // EE + NN self-loops
#define HH 4
#define CC 32
#define HC 128        // HH*CC
#define NBLK ((NN + 1023) / 1024)   // 49 scan blocks
#define EE2 (EE / 2)                // 400000 edge pairs

// ---------------- scratch (device globals: allocation-free) ----------------
__device__ __align__(16) __half g_lin16[NN * HC];  // messages (fp16, gather-only)
__device__ float g_act[NN * HC];
__device__ float g_alsrc[NN * HH];
__device__ float g_aldst[NN * HH];
__device__ __align__(16) float g_gmax[12];
__device__ int   g_csrc[ETOT];
__device__ int   g_rowptr[NN + 1];
__device__ int   g_fill[NN];
__device__ int   g_bsum[64];
__device__ int   g_is64;

// ---------------- streams for fork/join inside graph capture --------------
struct StreamPack {
    cudaStream_t sA, sB;
    cudaEvent_t evFork, evA, evB;
    StreamPack() {
        cudaStreamCreateWithFlags(&sA, cudaStreamNonBlocking);
        cudaStreamCreateWithFlags(&sB, cudaStreamNonBlocking);
        cudaEventCreateWithFlags(&evFork, cudaEventDisableTiming);
        cudaEventCreateWithFlags(&evA, cudaEventDisableTiming);
        cudaEventCreateWithFlags(&evB, cudaEventDisableTiming);
    }
};
static StreamPack g_sp;

__device__ __forceinline__ void atomicMaxF(float* addr, float v) {
    if (v >= 0.f) atomicMax((int*)addr, __float_as_int(v));
    else          atomicMin((unsigned int*)addr, __float_as_uint(v));
}

// ---- packed f32x2 helpers (FFMA2 path, sm_103a) ----
__device__ __forceinline__ unsigned long long pack2(float x) {
    unsigned long long r;
    asm("mov.b64 %0, {%1, %2};" : "=l"(r) : "f"(x), "f"(x));
    return r;
}
__device__ __forceinline__ void fma2(unsigned long long& d, unsigned long long a,
                                     unsigned long long b) {
    asm("fma.rn.f32x2 %0, %1, %2, %0;" : "+l"(d) : "l"(a), "l"(b));
}
__device__ __forceinline__ float2 unpack2(unsigned long long v) {
    float lo, hi;
    asm("mov.b64 {%0, %1}, %2;" : "=f"(lo), "=f"(hi) : "l"(v));
    return make_float2(lo, hi);
}

// ---------------- prologue: is64 detect + gmax init + g_fill = 1 ----------
__global__ void detect_zero_kernel(const int* __restrict__ buf) {
    int t = blockIdx.x * blockDim.x + threadIdx.x;
    if (t < NN) g_fill[t] = 1;
    if (blockIdx.x == 0 && threadIdx.x == 0) {
        int orv = 0;
        #pragma unroll
        for (int i = 1; i < 64; i += 2) orv |= buf[i];
        g_is64 = (orv == 0) ? 1 : 0;
    }
    if (blockIdx.x == 1 && threadIdx.x < 12) g_gmax[threadIdx.x] = -3.0e38f;
}

// degree count: 2 edges per thread, vectorized dst decode
__global__ void count_kernel(const int* __restrict__ buf) {
    int u = blockIdx.x * blockDim.x + threadIdx.x;
    if (u >= EE2) return;
    int d0, d1;
    if (g_is64) {
        int4 v = ((const int4*)buf)[EE2 + u];
        d0 = v.x; d1 = v.z;
    } else {
        int2 v = ((const int2*)(buf + EE))[u];
        d0 = v.x; d1 = v.y;
    }
    atomicAdd(&g_fill[d0], 1);
    atomicAdd(&g_fill[d1], 1);
}

// ---------------- 2-phase coalesced scan ----------------
__global__ void block_sum_kernel() {
    __shared__ int ws[32];
    int tid = threadIdx.x;
    int idx = blockIdx.x * 1024 + tid;
    int v = (idx < NN) ? g_fill[idx] : 0;
    #pragma unroll
    for (int o = 16; o >= 1; o >>= 1) v += __shfl_xor_sync(0xffffffff, v, o);
    int lane = tid & 31, wid = tid >> 5;
    if (lane == 0) ws[wid] = v;
    __syncthreads();
    if (wid == 0) {
        int w = ws[lane];
        #pragma unroll
        for (int o = 16; o >= 1; o >>= 1) w += __shfl_xor_sync(0xffffffff, w, o);
        if (lane == 0) g_bsum[blockIdx.x] = w;
    }
}

__global__ void rowptr_kernel() {
    __shared__ int ws[32];
    __shared__ int bofs;
    int tid = threadIdx.x;
    int idx = blockIdx.x * 1024 + tid;
    int lane = tid & 31, wid = tid >> 5;

    if (wid == 0) {
        int B = blockIdx.x;
        int a = (lane < B) ? g_bsum[lane] : 0;
        int b2 = (lane + 32 < B) ? g_bsum[lane + 32] : 0;
        int v = a + b2;
        #pragma unroll
        for (int o = 16; o >= 1; o >>= 1) v += __shfl_xor_sync(0xffffffff, v, o);
        if (lane == 0) bofs = v;
    }

    int c = (idx < NN) ? g_fill[idx] : 0;
    int v = c;
    #pragma unroll
    for (int o = 1; o < 32; o <<= 1) {
        int t2 = __shfl_up_sync(0xffffffff, v, o);
        if (lane >= o) v += t2;
    }
    if (lane == 31) ws[wid] = v;
    __syncthreads();
    if (wid == 0) {
        int w = ws[lane];
        #pragma unroll
        for (int o = 1; o < 32; o <<= 1) {
            int t2 = __shfl_up_sync(0xffffffff, w, o);
            if (lane >= o) w += t2;
        }
        ws[lane] = w;
    }
    __syncthreads();
    int excl = v - c + (wid > 0 ? ws[wid - 1] : 0) + bofs;
    if (idx < NN) {
        g_rowptr[idx] = excl;
        g_fill[idx] = excl;
    }
    if (idx == 0) g_rowptr[NN] = ETOT;
}

// fill CSR: 2 edges per thread, vectorized decode; self-loops in the tail
__global__ void csr_fill_kernel(const int* __restrict__ buf) {
    int u = blockIdx.x * blockDim.x + threadIdx.x;
    if (u < EE2) {
        int s0, s1, d0, d1;
        if (g_is64) {
            int4 sv = ((const int4*)buf)[u];
            int4 dv = ((const int4*)buf)[EE2 + u];
            s0 = sv.x; s1 = sv.z; d0 = dv.x; d1 = dv.z;
        } else {
            int2 sv = ((const int2*)buf)[u];
            int2 dv = ((const int2*)(buf + EE))[u];
            s0 = sv.x; s1 = sv.y; d0 = dv.x; d1 = dv.y;
        }
        g_csrc[atomicAdd(&g_fill[d0], 1)] = s0;
        g_csrc[atomicAdd(&g_fill[d1], 1)] = s1;
    } else {
        int v = u - EE2;
        if (v < NN) g_csrc[atomicAdd(&g_fill[v], 1)] = v;
    }
}

// ---------------- GEMM (FFMA2) + fused attention logits ----------------
template<int OUT, bool FROMACT>
__global__ __launch_bounds__(128) void gemm_al_kernel(
        const float* __restrict__ X, const float* __restrict__ W,
        const float* __restrict__ a_src, const float* __restrict__ a_dst,
        int gslot) {
    constexpr int NPB = (OUT == 128) ? 64 : 128;
    constexpr int CPT = (OUT == 128) ? 8 : 4;
    constexpr int CP2 = CPT / 2;
    constexpr int CGN = OUT / CPT;
    constexpr int KC  = 32;
    constexpr int NH  = (OUT == 128) ? 4 : 1;

    __shared__ __align__(16) float Xs[KC][NPB];
    __shared__ __align__(16) float Ws[KC][OUT];
    __shared__ float smax[NH];

    const float* __restrict__ Xp = FROMACT ? g_act : X;
    const int tid = threadIdx.x;
    const int cg = tid % CGN;
    const int ng = tid / CGN;
    const int row0 = blockIdx.x * NPB;

    if (tid < NH) smax[tid] = -3.0e38f;

    unsigned long long acc2[8][CP2];
    #pragma unroll
    for (int i = 0; i < 8; i++)
        #pragma unroll
        for (int j = 0; j < CP2; j++) acc2[i][j] = 0ull;

    for (int kc = 0; kc < HC; kc += KC) {
        __syncthreads();
        #pragma unroll
        for (int e = tid; e < KC * NPB / 4; e += 128) {
            int n  = e / (KC / 4);
            int kq = e % (KC / 4);
            int row = row0 + n; if (row >= NN) row = NN - 1;
            float4 v = *(const float4*)&Xp[row * HC + kc + kq * 4];
            Xs[kq * 4 + 0][n] = v.x;
            Xs[kq * 4 + 1][n] = v.y;
            Xs[kq * 4 + 2][n] = v.z;
            Xs[kq * 4 + 3][n] = v.w;
        }
        #pragma unroll
        for (int e = tid; e < KC * OUT / 4; e += 128) {
            ((float4*)&Ws[0][0])[e] = ((const float4*)&W[kc * OUT])[e];
        }
        __syncthreads();

        #pragma unroll
        for (int k = 0; k < KC; k++) {
            float4 xa = *(const float4*)&Xs[k][ng * 8];
            float4 xb = *(const float4*)&Xs[k][ng * 8 + 4];
            unsigned long long xd[8];
            xd[0] = pack2(xa.x); xd[1] = pack2(xa.y);
            xd[2] = pack2(xa.z); xd[3] = pack2(xa.w);
            xd[4] = pack2(xb.x); xd[5] = pack2(xb.y);
            xd[6] = pack2(xb.z); xd[7] = pack2(xb.w);

            unsigned long long wp[CP2];
            {
                double2 w0 = *(const double2*)&Ws[k][cg * CPT];
                wp[0] = __double_as_longlong(w0.x);
                wp[1] = __double_as_longlong(w0.y);
                if (CP2 == 4) {
                    double2 w1 = *(const double2*)&Ws[k][cg * CPT + 4];
                    wp[2] = __double_as_longlong(w1.x);
                    wp[3] = __double_as_longlong(w1.y);
                }
            }
            #pragma unroll
            for (int i = 0; i < 8; i++)
                #pragma unroll
                for (int j = 0; j < CP2; j++)
                    fma2(acc2[i][j], xd[i], wp[j]);
        }
    }

    float acc[8][CPT];
    #pragma unroll
    for (int i = 0; i < 8; i++)
        #pragma unroll
        for (int j = 0; j < CP2; j++) {
            float2 v = unpack2(acc2[i][j]);
            acc[i][2 * j] = v.x;
            acc[i][2 * j + 1] = v.y;
        }

    // store messages as fp16 (half2 pairs)
    #pragma unroll
    for (int i = 0; i < 8; i++) {
        int row = row0 + ng * 8 + i;
        if (row < NN) {
            #pragma unroll
            for (int j = 0; j < CP2; j++) {
                __half2 h = __float22half2_rn(make_float2(acc[i][2 * j], acc[i][2 * j + 1]));
                *(__half2*)&g_lin16[row * OUT + cg * CPT + 2 * j] = h;
            }
        }
    }

    // ---- fused al ----
    float asv[CPT], adv[CPT];
    {
        float4 a0 = *(const float4*)&a_src[cg * CPT];
        asv[0] = a0.x; asv[1] = a0.y; asv[2] = a0.z; asv[3] = a0.w;
        float4 d0 = *(const float4*)&a_dst[cg * CPT];
        adv[0] = d0.x; adv[1] = d0.y; adv[2] = d0.z; adv[3] = d0.w;
        if (CPT == 8) {
            float4 a1 = *(const float4*)&a_src[cg * CPT + 4];
            asv[4] = a1.x; asv[5] = a1.y; asv[6] = a1.z; asv[7] = a1.w;
            float4 d1 = *(const float4*)&a_dst[cg * CPT + 4];
            adv[4] = d1.x; adv[5] = d1.y; adv[6] = d1.z; adv[7] = d1.w;
        }
    }
    float ssp[8], sdp[8];
    #pragma unroll
    for (int i = 0; i < 8; i++) {
        float ss = 0.f, sd = 0.f;
        #pragma unroll
        for (int j = 0; j < CPT; j++) {
            ss += acc[i][j] * asv[j];
            sd += acc[i][j] * adv[j];
        }
        ssp[i] = ss; sdp[i] = sd;
    }
    #pragma unroll
    for (int i = 0; i < 8; i++) {
        ssp[i] += __shfl_xor_sync(0xffffffff, ssp[i], 1);
        sdp[i] += __shfl_xor_sync(0xffffffff, sdp[i], 1);
        ssp[i] += __shfl_xor_sync(0xffffffff, ssp[i], 2);
        sdp[i] += __shfl_xor_sync(0xffffffff, sdp[i], 2);
        if (OUT == 32) {
            ssp[i] += __shfl_xor_sync(0xffffffff, ssp[i], 4);
            sdp[i] += __shfl_xor_sync(0xffffffff, sdp[i], 4);
        }
    }
    float lmax = -3.0e38f;
    if (OUT == 128) {
        if ((cg & 3) == 0) {
            int h = cg >> 2;
            #pragma unroll
            for (int i = 0; i < 8; i++) {
                int row = row0 + ng * 8 + i;
                if (row < NN) {
                    g_alsrc[row * HH + h] = ssp[i];
                    g_aldst[row * HH + h] = sdp[i];
                    lmax = fmaxf(lmax, ssp[i]);
                }
            }
            atomicMaxF(&smax[h], lmax);
        }
    } else {
        if (cg == 0) {
            #pragma unroll
            for (int i = 0; i < 8; i++) {
                int row = row0 + ng * 8 + i;
                if (row < NN) {
                    g_alsrc[row] = ssp[i];
                    g_aldst[row] = sdp[i];
                    lmax = fmaxf(lmax, ssp[i]);
                }
            }
            atomicMaxF(&smax[0], lmax);
        }
    }
    __syncthreads();
    if (tid < NH) atomicMaxF(&g_gmax[gslot + tid], smax[tid]);
}

// ---------------- single-pass fused GAT aggregation (warp per dst) ----------
// gather unrolled x4: 8 independent 128B loads in flight per warp
__global__ __launch_bounds__(256) void gat_agg4_kernel(const float* __restrict__ b,
                                                       int gslot, int do_elu) {
    __shared__ int    ss[8][32];
    __shared__ float4 ww[8][32];

    int warp = (blockIdx.x * blockDim.x + threadIdx.x) >> 5;
    if (warp >= NN) return;
    int lane = threadIdx.x & 31;
    int wslot = (threadIdx.x >> 5) & 7;
    int d = warp;
    int start = g_rowptr[d], end = g_rowptr[d + 1];

    float4 ad = *(const float4*)&g_aldst[d * HH];
    float4 gm = *(const float4*)&g_gmax[gslot];
    float4 m;
    m.x = gm.x + ad.x; m.x = (m.x > 0.f) ? m.x : 0.2f * m.x;
    m.y = gm.y + ad.y; m.y = (m.y > 0.f) ? m.y : 0.2f * m.y;
    m.z = gm.z + ad.z; m.z = (m.z > 0.f) ? m.z : 0.2f * m.z;
    m.w = gm.w + ad.w; m.w = (m.w > 0.f) ? m.w : 0.2f * m.w;

    const int h0 = lane >> 4;
    const int h1 = 2 + h0;

    float4 denom = make_float4(0.f, 0.f, 0.f, 0.f);
    float a0x = 0.f, a0y = 0.f, a1x = 0.f, a1y = 0.f;

    for (int base = start; base < end; base += 32) {
        int i = base + lane;
        float4 w = make_float4(0.f, 0.f, 0.f, 0.f);
        int s = 0;
        if (i < end) {
            s = g_csrc[i];
            float4 v = *(const float4*)&g_alsrc[s * HH];
            v.x += ad.x; v.y += ad.y; v.z += ad.z; v.w += ad.w;
            v.x = (v.x > 0.f) ? v.x : 0.2f * v.x;
            v.y = (v.y > 0.f) ? v.y : 0.2f * v.y;
            v.z = (v.z > 0.f) ? v.z : 0.2f * v.z;
            v.w = (v.w > 0.f) ? v.w : 0.2f * v.w;
            w.x = __expf(v.x - m.x);
            w.y = __expf(v.y - m.y);
            w.z = __expf(v.z - m.z);
            w.w = __expf(v.w - m.w);
        }
        denom.x += w.x; denom.y += w.y; denom.z += w.z; denom.w += w.w;
        ss[wslot][lane] = s;
        ww[wslot][lane] = w;
        __syncwarp();
        int n = min(32, end - base);
        int j = 0;
        // unroll by 4: 8 independent 128B loads in flight
        for (; j + 3 < n; j += 4) {
            int sj0 = ss[wslot][j];
            int sj1 = ss[wslot][j + 1];
            int sj2 = ss[wslot][j + 2];
            int sj3 = ss[wslot][j + 3];
            const float* w0p = (const float*)&ww[wslot][j];
            const float* w1p = (const float*)&ww[wslot][j + 1];
            const float* w2p = (const float*)&ww[wslot][j + 2];
            const float* w3p = (const float*)&ww[wslot][j + 3];
            const __half2* hp0 = (const __half2*)(g_lin16 + sj0 * HC);
            const __half2* hp1 = (const __half2*)(g_lin16 + sj1 * HC);
            const __half2* hp2 = (const __half2*)(g_lin16 + sj2 * HC);
            const __half2* hp3 = (const __half2*)(g_lin16 + sj3 * HC);
            __half2 r00 = hp0[lane], r01 = hp0[32 + lane];
            __half2 r10 = hp1[lane], r11 = hp1[32 + lane];
            __half2 r20 = hp2[lane], r21 = hp2[32 + lane];
            __half2 r30 = hp3[lane], r31 = hp3[32 + lane];
            float2 p;
            float wa, wb;
            wa = w0p[h0]; wb = w0p[h1];
            p = __half22float2(r00); a0x += wa * p.x; a0y += wa * p.y;
            p = __half22float2(r01); a1x += wb * p.x; a1y += wb * p.y;
            wa = w1p[h0]; wb = w1p[h1];
            p = __half22float2(r10); a0x += wa * p.x; a0y += wa * p.y;
            p = __half22float2(r11); a1x += wb * p.x; a1y += wb * p.y;
            wa = w2p[h0]; wb = w2p[h1];
            p = __half22float2(r20); a0x += wa * p.x; a0y += wa * p.y;
            p = __half22float2(r21); a1x += wb * p.x; a1y += wb * p.y;
            wa = w3p[h0]; wb = w3p[h1];
            p = __half22float2(r30); a0x += wa * p.x; a0y += wa * p.y;
            p = __half22float2(r31); a1x += wb * p.x; a1y += wb * p.y;
        }
        for (; j < n; j++) {
            int sj = ss[wslot][j];
            const float* wjp = (const float*)&ww[wslot][j];
            const __half2* hp = (const __half2*)(g_lin16 + sj * HC);
            float2 m0 = __half22float2(hp[lane]);
            float2 m1 = __half22float2(hp[32 + lane]);
            float w0 = wjp[h0], w1 = wjp[h1];
            a0x += w0 * m0.x; a0y += w0 * m0.y;
            a1x += w1 * m1.x; a1y += w1 * m1.y;
        }
        __syncwarp();
    }

    #pragma unroll
    for (int o = 16; o >= 1; o >>= 1) {
        denom.x += __shfl_xor_sync(0xffffffff, denom.x, o);
        denom.y += __shfl_xor_sync(0xffffffff, denom.y, o);
        denom.z += __shfl_xor_sync(0xffffffff, denom.z, o);
        denom.w += __shfl_xor_sync(0xffffffff, denom.w, o);
    }
    float rd0 = 1.f / ((h0 == 0 ? denom.x : denom.y) + 1e-16f);
    float rd1 = 1.f / ((h1 == 2 ? denom.z : denom.w) + 1e-16f);

    float2 b0 = *(const float2*)&b[2 * lane];
    float2 b1 = *(const float2*)&b[64 + 2 * lane];
    a0x = a0x * rd0 + b0.x;
    a0y = a0y * rd0 + b0.y;
    a1x = a1x * rd1 + b1.x;
    a1y = a1y * rd1 + b1.y;
    if (do_elu) {
        a0x = (a0x > 0.f) ? a0x : (__expf(a0x) - 1.f);
        a0y = (a0y > 0.f) ? a0y : (__expf(a0y) - 1.f);
        a1x = (a1x > 0.f) ? a1x : (__expf(a1x) - 1.f);
        a1y = (a1y > 0.f) ? a1y : (__expf(a1y) - 1.f);
    }
    float* o = g_act + d * HC;
    *(float2*)&o[2 * lane] = make_float2(a0x, a0y);
    *(float2*)&o[64 + 2 * lane] = make_float2(a1x, a1y);
}

// layer 3 (H=1) fused with classifier head + embedding write
__global__ __launch_bounds__(256) void gat_agg1_head_kernel(
        const float* __restrict__ b, const float* __restrict__ Wc,
        const float* __restrict__ bc, float* __restrict__ out) {
    __shared__ int   ss[8][32];
    __shared__ float ww[8][32];

    int warp = (blockIdx.x * blockDim.x + threadIdx.x) >> 5;
    if (warp >= NN) return;
    int lane = threadIdx.x & 31;
    int wslot = (threadIdx.x >> 5) & 7;
    int d = warp;
    int start = g_rowptr[d], end = g_rowptr[d + 1];

    float ad = g_aldst[d];
    float gm = g_gmax[8];
    float m = gm + ad; m = (m > 0.f) ? m : 0.2f * m;

    float denom = 0.f;
    float acc = 0.f;

    for (int base = start; base < end; base += 32) {
        int i = base + lane;
        float w = 0.f;
        int s = 0;
        if (i < end) {
            s = g_csrc[i];
            float v = g_alsrc[s] + ad;
            v = (v > 0.f) ? v : 0.2f * v;
            w = __expf(v - m);
        }
        denom += w;
        ss[wslot][lane] = s;
        ww[wslot][lane] = w;
        __syncwarp();
        int n = min(32, end - base);
        int j = 0;
        for (; j + 3 < n; j += 4) {
            float v0 = __half2float(g_lin16[ss[wslot][j] * CC + lane]);
            float v1 = __half2float(g_lin16[ss[wslot][j + 1] * CC + lane]);
            float v2 = __half2float(g_lin16[ss[wslot][j + 2] * CC + lane]);
            float v3 = __half2float(g_lin16[ss[wslot][j + 3] * CC + lane]);
            acc += ww[wslot][j] * v0 + ww[wslot][j + 1] * v1
                 + ww[wslot][j + 2] * v2 + ww[wslot][j + 3] * v3;
        }
        for (; j < n; j++) {
            acc += ww[wslot][j] * __half2float(g_lin16[ss[wslot][j] * CC + lane]);
        }
        __syncwarp();
    }
    #pragma unroll
    for (int o = 16; o >= 1; o >>= 1)
        denom += __shfl_xor_sync(0xffffffff, denom, o);

    float h = acc / (denom + 1e-16f) + b[lane];

    out[NN * 2 + d * CC + lane] = h;

    float o0 = h * Wc[lane * 2 + 0];
    float o1 = h * Wc[lane * 2 + 1];
    #pragma unroll
    for (int o = 16; o >= 1; o >>= 1) {
        o0 += __shfl_xor_sync(0xffffffff, o0, o);
        o1 += __shfl_xor_sync(0xffffffff, o1, o);
    }
    if (lane == 0) {
        out[d * 2 + 0] = o0 + bc[0];
        out[d * 2 + 1] = o1 + bc[1];
    }
}

// ---------------- launch ----------------
extern "C" void kernel_launch(void* const* d_in, const int* in_sizes, int n_in,
                              void* d_out, int out_size) {
    const float* x   = (const float*)d_in[0];
    const int*   ei  = (const int*)d_in[1];
    const float* W1  = (const float*)d_in[2];
    const float* a1s = (const float*)d_in[3];
    const float* a1d = (const float*)d_in[4];
    const float* b1  = (const float*)d_in[5];
    const float* W2  = (const float*)d_in[6];
    const float* a2s = (const float*)d_in[7];
    const float* a2d = (const float*)d_in[8];
    const float* b2  = (const float*)d_in[9];
    const float* W3  = (const float*)d_in[10];
    const float* a3s = (const float*)d_in[11];
    const float* a3d = (const float*)d_in[12];
    const float* b3  = (const float*)d_in[13];
    const float* Wc  = (const float*)d_in[14];
    const float* bc  = (const float*)d_in[15];
    float* out = (float*)d_out;

    const int T = 256;
    const int gN = (NN + T - 1) / T;
    const int gW = (NN * 32 + T - 1) / T;
    const int gC = (EE2 + T - 1) / T;
    const int gF = (EE2 + NN + T - 1) / T;

    cudaStream_t s0 = 0;
    cudaStream_t sA = g_sp.sA;
    cudaStream_t sB = g_sp.sB;

    detect_zero_kernel<<<gN, T, 0, s0>>>(ei);

    cudaEventRecord(g_sp.evFork, s0);
    cudaStreamWaitEvent(sA, g_sp.evFork, 0);
    cudaStreamWaitEvent(sB, g_sp.evFork, 0);

    // ---- branch A: CSR build ----
    count_kernel<<<gC, T, 0, sA>>>(ei);
    block_sum_kernel<<<NBLK, 1024, 0, sA>>>();
    rowptr_kernel<<<NBLK, 1024, 0, sA>>>();
    csr_fill_kernel<<<gF, T, 0, sA>>>(ei);
    cudaEventRecord(g_sp.evA, sA);

    // ---- branch B: layer-1 GEMM + attention logits ----
    gemm_al_kernel<128, false><<<(NN + 63) / 64, 128, 0, sB>>>(x, W1, a1s, a1d, 0);
    cudaEventRecord(g_sp.evB, sB);

    cudaStreamWaitEvent(s0, g_sp.evA, 0);
    cudaStreamWaitEvent(s0, g_sp.evB, 0);

    // ---- serial layer chain ----
    gat_agg4_kernel<<<gW, T, 0, s0>>>(b1, 0, 1);
    gemm_al_kernel<128, true><<<(NN + 63) / 64, 128, 0, s0>>>(nullptr, W2, a2s, a2d, 4);
    gat_agg4_kernel<<<gW, T, 0, s0>>>(b2, 4, 1);
    gemm_al_kernel<32, true><<<(NN + 127) / 128, 128, 0, s0>>>(nullptr, W3, a3s, a3d, 8);
    gat_agg1_head_kernel<<<gW, T, 0, s0>>>(b3, Wc, bc, out);
}

// round 16
// speedup vs baseline: 1.4270x; 1.0021x over previous
#include <cuda_runtime.h>
#include <cuda_fp16.h>

// Problem constants (fixed by the dataset)
#define NN 50000
#define EE 800000
#define ETOT 850000   // EE + NN self-loops
#define HH 4
#define CC 32
#define HC 128        // HH*CC
#define NBLK ((NN + 1023) / 1024)   // 49 scan blocks
#define EE2 (EE / 2)                // 400000 edge pairs

// ---------------- scratch (device globals: allocation-free) ----------------
__device__ __align__(16) __half g_lin16[NN * HC];  // messages (fp16, gather-only)
__device__ float g_act[NN * HC];
__device__ float g_alsrc[NN * HH];
__device__ float g_aldst[NN * HH];
__device__ __align__(16) float g_gmax[12];
__device__ int   g_csrc[ETOT];
__device__ int   g_rowptr[NN + 1];
__device__ int   g_fill[NN];
__device__ int   g_bsum[64];
__device__ int   g_is64;

// ---------------- streams for fork/join inside graph capture --------------
struct StreamPack {
    cudaStream_t sA, sB;
    cudaEvent_t evFork, evA, evB;
    StreamPack() {
        cudaStreamCreateWithFlags(&sA, cudaStreamNonBlocking);
        cudaStreamCreateWithFlags(&sB, cudaStreamNonBlocking);
        cudaEventCreateWithFlags(&evFork, cudaEventDisableTiming);
        cudaEventCreateWithFlags(&evA, cudaEventDisableTiming);
        cudaEventCreateWithFlags(&evB, cudaEventDisableTiming);
    }
};
static StreamPack g_sp;

__device__ __forceinline__ void atomicMaxF(float* addr, float v) {
    if (v >= 0.f) atomicMax((int*)addr, __float_as_int(v));
    else          atomicMin((unsigned int*)addr, __float_as_uint(v));
}

// ---- packed f32x2 helpers (FFMA2 path, sm_103a) ----
__device__ __forceinline__ unsigned long long pack2(float x) {
    unsigned long long r;
    asm("mov.b64 %0, {%1, %2};" : "=l"(r) : "f"(x), "f"(x));
    return r;
}
__device__ __forceinline__ void fma2(unsigned long long& d, unsigned long long a,
                                     unsigned long long b) {
    asm("fma.rn.f32x2 %0, %1, %2, %0;" : "+l"(d) : "l"(a), "l"(b));
}
__device__ __forceinline__ float2 unpack2(unsigned long long v) {
    float lo, hi;
    asm("mov.b64 {%0, %1}, %2;" : "=f"(lo), "=f"(hi) : "l"(v));
    return make_float2(lo, hi);
}

// ---------------- prologue: is64 detect + gmax init + g_fill = 1 ----------
__global__ void detect_zero_kernel(const int* __restrict__ buf) {
    int t = blockIdx.x * blockDim.x + threadIdx.x;
    if (t < NN) g_fill[t] = 1;
    if (blockIdx.x == 0 && threadIdx.x == 0) {
        int orv = 0;
        #pragma unroll
        for (int i = 1; i < 64; i += 2) orv |= buf[i];
        g_is64 = (orv == 0) ? 1 : 0;
    }
    if (blockIdx.x == 1 && threadIdx.x < 12) g_gmax[threadIdx.x] = -3.0e38f;
}

// degree count: 2 edges per thread, vectorized dst decode
__global__ void count_kernel(const int* __restrict__ buf) {
    int u = blockIdx.x * blockDim.x + threadIdx.x;
    if (u >= EE2) return;
    int d0, d1;
    if (g_is64) {
        int4 v = ((const int4*)buf)[EE2 + u];
        d0 = v.x; d1 = v.z;
    } else {
        int2 v = ((const int2*)(buf + EE))[u];
        d0 = v.x; d1 = v.y;
    }
    atomicAdd(&g_fill[d0], 1);
    atomicAdd(&g_fill[d1], 1);
}

// ---------------- 2-phase coalesced scan ----------------
__global__ void block_sum_kernel() {
    __shared__ int ws[32];
    int tid = threadIdx.x;
    int idx = blockIdx.x * 1024 + tid;
    int v = (idx < NN) ? g_fill[idx] : 0;
    #pragma unroll
    for (int o = 16; o >= 1; o >>= 1) v += __shfl_xor_sync(0xffffffff, v, o);
    int lane = tid & 31, wid = tid >> 5;
    if (lane == 0) ws[wid] = v;
    __syncthreads();
    if (wid == 0) {
        int w = ws[lane];
        #pragma unroll
        for (int o = 16; o >= 1; o >>= 1) w += __shfl_xor_sync(0xffffffff, w, o);
        if (lane == 0) g_bsum[blockIdx.x] = w;
    }
}

__global__ void rowptr_kernel() {
    __shared__ int ws[32];
    __shared__ int bofs;
    int tid = threadIdx.x;
    int idx = blockIdx.x * 1024 + tid;
    int lane = tid & 31, wid = tid >> 5;

    if (wid == 0) {
        int B = blockIdx.x;
        int a = (lane < B) ? g_bsum[lane] : 0;
        int b2 = (lane + 32 < B) ? g_bsum[lane + 32] : 0;
        int v = a + b2;
        #pragma unroll
        for (int o = 16; o >= 1; o >>= 1) v += __shfl_xor_sync(0xffffffff, v, o);
        if (lane == 0) bofs = v;
    }

    int c = (idx < NN) ? g_fill[idx] : 0;
    int v = c;
    #pragma unroll
    for (int o = 1; o < 32; o <<= 1) {
        int t2 = __shfl_up_sync(0xffffffff, v, o);
        if (lane >= o) v += t2;
    }
    if (lane == 31) ws[wid] = v;
    __syncthreads();
    if (wid == 0) {
        int w = ws[lane];
        #pragma unroll
        for (int o = 1; o < 32; o <<= 1) {
            int t2 = __shfl_up_sync(0xffffffff, w, o);
            if (lane >= o) w += t2;
        }
        ws[lane] = w;
    }
    __syncthreads();
    int excl = v - c + (wid > 0 ? ws[wid - 1] : 0) + bofs;
    if (idx < NN) {
        g_rowptr[idx] = excl;
        g_fill[idx] = excl;
    }
    if (idx == 0) g_rowptr[NN] = ETOT;
}

// fill CSR: 2 edges per thread, vectorized decode; self-loops in the tail
__global__ void csr_fill_kernel(const int* __restrict__ buf) {
    int u = blockIdx.x * blockDim.x + threadIdx.x;
    if (u < EE2) {
        int s0, s1, d0, d1;
        if (g_is64) {
            int4 sv = ((const int4*)buf)[u];
            int4 dv = ((const int4*)buf)[EE2 + u];
            s0 = sv.x; s1 = sv.z; d0 = dv.x; d1 = dv.z;
        } else {
            int2 sv = ((const int2*)buf)[u];
            int2 dv = ((const int2*)(buf + EE))[u];
            s0 = sv.x; s1 = sv.y; d0 = dv.x; d1 = dv.y;
        }
        g_csrc[atomicAdd(&g_fill[d0], 1)] = s0;
        g_csrc[atomicAdd(&g_fill[d1], 1)] = s1;
    } else {
        int v = u - EE2;
        if (v < NN) g_csrc[atomicAdd(&g_fill[v], 1)] = v;
    }
}

// ---------------- GEMM (FFMA2) + fused attention logits ----------------
template<int OUT, bool FROMACT>
__global__ __launch_bounds__(128) void gemm_al_kernel(
        const float* __restrict__ X, const float* __restrict__ W,
        const float* __restrict__ a_src, const float* __restrict__ a_dst,
        int gslot) {
    constexpr int NPB = (OUT == 128) ? 64 : 128;
    constexpr int CPT = (OUT == 128) ? 8 : 4;
    constexpr int CP2 = CPT / 2;
    constexpr int CGN = OUT / CPT;
    constexpr int KC  = 32;
    constexpr int NH  = (OUT == 128) ? 4 : 1;

    __shared__ __align__(16) float Xs[KC][NPB];
    __shared__ __align__(16) float Ws[KC][OUT];
    __shared__ float smax[NH];

    const float* __restrict__ Xp = FROMACT ? g_act : X;
    const int tid = threadIdx.x;
    const int cg = tid % CGN;
    const int ng = tid / CGN;
    const int row0 = blockIdx.x * NPB;

    if (tid < NH) smax[tid] = -3.0e38f;

    unsigned long long acc2[8][CP2];
    #pragma unroll
    for (int i = 0; i < 8; i++)
        #pragma unroll
        for (int j = 0; j < CP2; j++) acc2[i][j] = 0ull;

    for (int kc = 0; kc < HC; kc += KC) {
        __syncthreads();
        #pragma unroll
        for (int e = tid; e < KC * NPB / 4; e += 128) {
            int n  = e / (KC / 4);
            int kq = e % (KC / 4);
            int row = row0 + n; if (row >= NN) row = NN - 1;
            float4 v = *(const float4*)&Xp[row * HC + kc + kq * 4];
            Xs[kq * 4 + 0][n] = v.x;
            Xs[kq * 4 + 1][n] = v.y;
            Xs[kq * 4 + 2][n] = v.z;
            Xs[kq * 4 + 3][n] = v.w;
        }
        #pragma unroll
        for (int e = tid; e < KC * OUT / 4; e += 128) {
            ((float4*)&Ws[0][0])[e] = ((const float4*)&W[kc * OUT])[e];
        }
        __syncthreads();

        #pragma unroll
        for (int k = 0; k < KC; k++) {
            float4 xa = *(const float4*)&Xs[k][ng * 8];
            float4 xb = *(const float4*)&Xs[k][ng * 8 + 4];
            unsigned long long xd[8];
            xd[0] = pack2(xa.x); xd[1] = pack2(xa.y);
            xd[2] = pack2(xa.z); xd[3] = pack2(xa.w);
            xd[4] = pack2(xb.x); xd[5] = pack2(xb.y);
            xd[6] = pack2(xb.z); xd[7] = pack2(xb.w);

            unsigned long long wp[CP2];
            {
                double2 w0 = *(const double2*)&Ws[k][cg * CPT];
                wp[0] = __double_as_longlong(w0.x);
                wp[1] = __double_as_longlong(w0.y);
                if (CP2 == 4) {
                    double2 w1 = *(const double2*)&Ws[k][cg * CPT + 4];
                    wp[2] = __double_as_longlong(w1.x);
                    wp[3] = __double_as_longlong(w1.y);
                }
            }
            #pragma unroll
            for (int i = 0; i < 8; i++)
                #pragma unroll
                for (int j = 0; j < CP2; j++)
                    fma2(acc2[i][j], xd[i], wp[j]);
        }
    }

    float acc[8][CPT];
    #pragma unroll
    for (int i = 0; i < 8; i++)
        #pragma unroll
        for (int j = 0; j < CP2; j++) {
            float2 v = unpack2(acc2[i][j]);
            acc[i][2 * j] = v.x;
            acc[i][2 * j + 1] = v.y;
        }

    // store messages as fp16 (half2 pairs)
    #pragma unroll
    for (int i = 0; i < 8; i++) {
        int row = row0 + ng * 8 + i;
        if (row < NN) {
            #pragma unroll
            for (int j = 0; j < CP2; j++) {
                __half2 h = __float22half2_rn(make_float2(acc[i][2 * j], acc[i][2 * j + 1]));
                *(__half2*)&g_lin16[row * OUT + cg * CPT + 2 * j] = h;
            }
        }
    }

    // ---- fused al ----
    float asv[CPT], adv[CPT];
    {
        float4 a0 = *(const float4*)&a_src[cg * CPT];
        asv[0] = a0.x; asv[1] = a0.y; asv[2] = a0.z; asv[3] = a0.w;
        float4 d0 = *(const float4*)&a_dst[cg * CPT];
        adv[0] = d0.x; adv[1] = d0.y; adv[2] = d0.z; adv[3] = d0.w;
        if (CPT == 8) {
            float4 a1 = *(const float4*)&a_src[cg * CPT + 4];
            asv[4] = a1.x; asv[5] = a1.y; asv[6] = a1.z; asv[7] = a1.w;
            float4 d1 = *(const float4*)&a_dst[cg * CPT + 4];
            adv[4] = d1.x; adv[5] = d1.y; adv[6] = d1.z; adv[7] = d1.w;
        }
    }
    float ssp[8], sdp[8];
    #pragma unroll
    for (int i = 0; i < 8; i++) {
        float ss = 0.f, sd = 0.f;
        #pragma unroll
        for (int j = 0; j < CPT; j++) {
            ss += acc[i][j] * asv[j];
            sd += acc[i][j] * adv[j];
        }
        ssp[i] = ss; sdp[i] = sd;
    }
    #pragma unroll
    for (int i = 0; i < 8; i++) {
        ssp[i] += __shfl_xor_sync(0xffffffff, ssp[i], 1);
        sdp[i] += __shfl_xor_sync(0xffffffff, sdp[i], 1);
        ssp[i] += __shfl_xor_sync(0xffffffff, ssp[i], 2);
        sdp[i] += __shfl_xor_sync(0xffffffff, sdp[i], 2);
        if (OUT == 32) {
            ssp[i] += __shfl_xor_sync(0xffffffff, ssp[i], 4);
            sdp[i] += __shfl_xor_sync(0xffffffff, sdp[i], 4);
        }
    }
    float lmax = -3.0e38f;
    if (OUT == 128) {
        if ((cg & 3) == 0) {
            int h = cg >> 2;
            #pragma unroll
            for (int i = 0; i < 8; i++) {
                int row = row0 + ng * 8 + i;
                if (row < NN) {
                    g_alsrc[row * HH + h] = ssp[i];
                    g_aldst[row * HH + h] = sdp[i];
                    lmax = fmaxf(lmax, ssp[i]);
                }
            }
            atomicMaxF(&smax[h], lmax);
        }
    } else {
        if (cg == 0) {
            #pragma unroll
            for (int i = 0; i < 8; i++) {
                int row = row0 + ng * 8 + i;
                if (row < NN) {
                    g_alsrc[row] = ssp[i];
                    g_aldst[row] = sdp[i];
                    lmax = fmaxf(lmax, ssp[i]);
                }
            }
            atomicMaxF(&smax[0], lmax);
        }
    }
    __syncthreads();
    if (tid < NH) atomicMaxF(&g_gmax[gslot + tid], smax[tid]);
}

// ---------------- single-pass fused GAT aggregation (warp per dst) ----------
// gather unrolled x8: 16 independent 128B loads in flight per warp
__global__ __launch_bounds__(256) void gat_agg4_kernel(const float* __restrict__ b,
                                                       int gslot, int do_elu) {
    __shared__ int    ss[8][32];
    __shared__ float4 ww[8][32];

    int warp = (blockIdx.x * blockDim.x + threadIdx.x) >> 5;
    if (warp >= NN) return;
    int lane = threadIdx.x & 31;
    int wslot = (threadIdx.x >> 5) & 7;
    int d = warp;
    int start = g_rowptr[d], end = g_rowptr[d + 1];

    float4 ad = *(const float4*)&g_aldst[d * HH];
    float4 gm = *(const float4*)&g_gmax[gslot];
    float4 m;
    m.x = gm.x + ad.x; m.x = (m.x > 0.f) ? m.x : 0.2f * m.x;
    m.y = gm.y + ad.y; m.y = (m.y > 0.f) ? m.y : 0.2f * m.y;
    m.z = gm.z + ad.z; m.z = (m.z > 0.f) ? m.z : 0.2f * m.z;
    m.w = gm.w + ad.w; m.w = (m.w > 0.f) ? m.w : 0.2f * m.w;

    const int h0 = lane >> 4;
    const int h1 = 2 + h0;

    float4 denom = make_float4(0.f, 0.f, 0.f, 0.f);
    float a0x = 0.f, a0y = 0.f, a1x = 0.f, a1y = 0.f;

    for (int base = start; base < end; base += 32) {
        int i = base + lane;
        float4 w = make_float4(0.f, 0.f, 0.f, 0.f);
        int s = 0;
        if (i < end) {
            s = g_csrc[i];
            float4 v = *(const float4*)&g_alsrc[s * HH];
            v.x += ad.x; v.y += ad.y; v.z += ad.z; v.w += ad.w;
            v.x = (v.x > 0.f) ? v.x : 0.2f * v.x;
            v.y = (v.y > 0.f) ? v.y : 0.2f * v.y;
            v.z = (v.z > 0.f) ? v.z : 0.2f * v.z;
            v.w = (v.w > 0.f) ? v.w : 0.2f * v.w;
            w.x = __expf(v.x - m.x);
            w.y = __expf(v.y - m.y);
            w.z = __expf(v.z - m.z);
            w.w = __expf(v.w - m.w);
        }
        denom.x += w.x; denom.y += w.y; denom.z += w.z; denom.w += w.w;
        ss[wslot][lane] = s;
        ww[wslot][lane] = w;
        __syncwarp();
        int n = min(32, end - base);
        int j = 0;
        // unroll by 8: 16 independent 128B loads in flight
        for (; j + 7 < n; j += 8) {
            __half2 r0[8], r1[8];
            #pragma unroll
            for (int q = 0; q < 8; q++) {
                const __half2* hp = (const __half2*)(g_lin16 + ss[wslot][j + q] * HC);
                r0[q] = hp[lane];
                r1[q] = hp[32 + lane];
            }
            #pragma unroll
            for (int q = 0; q < 8; q++) {
                const float* wp = (const float*)&ww[wslot][j + q];
                float wa = wp[h0], wb = wp[h1];
                float2 p0 = __half22float2(r0[q]);
                float2 p1 = __half22float2(r1[q]);
                a0x += wa * p0.x; a0y += wa * p0.y;
                a1x += wb * p1.x; a1y += wb * p1.y;
            }
        }
        // unroll by 4 tail
        for (; j + 3 < n; j += 4) {
            __half2 r0[4], r1[4];
            #pragma unroll
            for (int q = 0; q < 4; q++) {
                const __half2* hp = (const __half2*)(g_lin16 + ss[wslot][j + q] * HC);
                r0[q] = hp[lane];
                r1[q] = hp[32 + lane];
            }
            #pragma unroll
            for (int q = 0; q < 4; q++) {
                const float* wp = (const float*)&ww[wslot][j + q];
                float wa = wp[h0], wb = wp[h1];
                float2 p0 = __half22float2(r0[q]);
                float2 p1 = __half22float2(r1[q]);
                a0x += wa * p0.x; a0y += wa * p0.y;
                a1x += wb * p1.x; a1y += wb * p1.y;
            }
        }
        for (; j < n; j++) {
            int sj = ss[wslot][j];
            const float* wjp = (const float*)&ww[wslot][j];
            const __half2* hp = (const __half2*)(g_lin16 + sj * HC);
            float2 m0 = __half22float2(hp[lane]);
            float2 m1 = __half22float2(hp[32 + lane]);
            float w0 = wjp[h0], w1 = wjp[h1];
            a0x += w0 * m0.x; a0y += w0 * m0.y;
            a1x += w1 * m1.x; a1y += w1 * m1.y;
        }
        __syncwarp();
    }

    #pragma unroll
    for (int o = 16; o >= 1; o >>= 1) {
        denom.x += __shfl_xor_sync(0xffffffff, denom.x, o);
        denom.y += __shfl_xor_sync(0xffffffff, denom.y, o);
        denom.z += __shfl_xor_sync(0xffffffff, denom.z, o);
        denom.w += __shfl_xor_sync(0xffffffff, denom.w, o);
    }
    float rd0 = 1.f / ((h0 == 0 ? denom.x : denom.y) + 1e-16f);
    float rd1 = 1.f / ((h1 == 2 ? denom.z : denom.w) + 1e-16f);

    float2 b0 = *(const float2*)&b[2 * lane];
    float2 b1 = *(const float2*)&b[64 + 2 * lane];
    a0x = a0x * rd0 + b0.x;
    a0y = a0y * rd0 + b0.y;
    a1x = a1x * rd1 + b1.x;
    a1y = a1y * rd1 + b1.y;
    if (do_elu) {
        a0x = (a0x > 0.f) ? a0x : (__expf(a0x) - 1.f);
        a0y = (a0y > 0.f) ? a0y : (__expf(a0y) - 1.f);
        a1x = (a1x > 0.f) ? a1x : (__expf(a1x) - 1.f);
        a1y = (a1y > 0.f) ? a1y : (__expf(a1y) - 1.f);
    }
    float* o = g_act + d * HC;
    *(float2*)&o[2 * lane] = make_float2(a0x, a0y);
    *(float2*)&o[64 + 2 * lane] = make_float2(a1x, a1y);
}

// layer 3 (H=1) fused with classifier head + embedding write
__global__ __launch_bounds__(256) void gat_agg1_head_kernel(
        const float* __restrict__ b, const float* __restrict__ Wc,
        const float* __restrict__ bc, float* __restrict__ out) {
    __shared__ int   ss[8][32];
    __shared__ float ww[8][32];

    int warp = (blockIdx.x * blockDim.x + threadIdx.x) >> 5;
    if (warp >= NN) return;
    int lane = threadIdx.x & 31;
    int wslot = (threadIdx.x >> 5) & 7;
    int d = warp;
    int start = g_rowptr[d], end = g_rowptr[d + 1];

    float ad = g_aldst[d];
    float gm = g_gmax[8];
    float m = gm + ad; m = (m > 0.f) ? m : 0.2f * m;

    float denom = 0.f;
    float acc = 0.f;

    for (int base = start; base < end; base += 32) {
        int i = base + lane;
        float w = 0.f;
        int s = 0;
        if (i < end) {
            s = g_csrc[i];
            float v = g_alsrc[s] + ad;
            v = (v > 0.f) ? v : 0.2f * v;
            w = __expf(v - m);
        }
        denom += w;
        ss[wslot][lane] = s;
        ww[wslot][lane] = w;
        __syncwarp();
        int n = min(32, end - base);
        int j = 0;
        for (; j + 7 < n; j += 8) {
            float v[8];
            #pragma unroll
            for (int q = 0; q < 8; q++)
                v[q] = __half2float(g_lin16[ss[wslot][j + q] * CC + lane]);
            #pragma unroll
            for (int q = 0; q < 8; q++)
                acc += ww[wslot][j + q] * v[q];
        }
        for (; j + 3 < n; j += 4) {
            float v0 = __half2float(g_lin16[ss[wslot][j] * CC + lane]);
            float v1 = __half2float(g_lin16[ss[wslot][j + 1] * CC + lane]);
            float v2 = __half2float(g_lin16[ss[wslot][j + 2] * CC + lane]);
            float v3 = __half2float(g_lin16[ss[wslot][j + 3] * CC + lane]);
            acc += ww[wslot][j] * v0 + ww[wslot][j + 1] * v1
                 + ww[wslot][j + 2] * v2 + ww[wslot][j + 3] * v3;
        }
        for (; j < n; j++) {
            acc += ww[wslot][j] * __half2float(g_lin16[ss[wslot][j] * CC + lane]);
        }
        __syncwarp();
    }
    #pragma unroll
    for (int o = 16; o >= 1; o >>= 1)
        denom += __shfl_xor_sync(0xffffffff, denom, o);

    float h = acc / (denom + 1e-16f) + b[lane];

    out[NN * 2 + d * CC + lane] = h;

    float o0 = h * Wc[lane * 2 + 0];
    float o1 = h * Wc[lane * 2 + 1];
    #pragma unroll
    for (int o = 16; o >= 1; o >>= 1) {
        o0 += __shfl_xor_sync(0xffffffff, o0, o);
        o1 += __shfl_xor_sync(0xffffffff, o1, o);
    }
    if (lane == 0) {
        out[d * 2 + 0] = o0 + bc[0];
        out[d * 2 + 1] = o1 + bc[1];
    }
}

// ---------------- launch ----------------
extern "C" void kernel_launch(void* const* d_in, const int* in_sizes, int n_in,
                              void* d_out, int out_size) {
    const float* x   = (const float*)d_in[0];
    const int*   ei  = (const int*)d_in[1];
    const float* W1  = (const float*)d_in[2];
    const float* a1s = (const float*)d_in[3];
    const float* a1d = (const float*)d_in[4];
    const float* b1  = (const float*)d_in[5];
    const float* W2  = (const float*)d_in[6];
    const float* a2s = (const float*)d_in[7];
    const float* a2d = (const float*)d_in[8];
    const float* b2  = (const float*)d_in[9];
    const float* W3  = (const float*)d_in[10];
    const float* a3s = (const float*)d_in[11];
    const float* a3d = (const float*)d_in[12];
    const float* b3  = (const float*)d_in[13];
    const float* Wc  = (const float*)d_in[14];
    const float* bc  = (const float*)d_in[15];
    float* out = (float*)d_out;

    const int T = 256;
    const int gN = (NN + T - 1) / T;
    const int gW = (NN * 32 + T - 1) / T;
    const int gC = (EE2 + T - 1) / T;
    const int gF = (EE2 + NN + T - 1) / T;

    cudaStream_t s0 = 0;
    cudaStream_t sA = g_sp.sA;
    cudaStream_t sB = g_sp.sB;

    detect_zero_kernel<<<gN, T, 0, s0>>>(ei);

    cudaEventRecord(g_sp.evFork, s0);
    cudaStreamWaitEvent(sA, g_sp.evFork, 0);
    cudaStreamWaitEvent(sB, g_sp.evFork, 0);

    // ---- branch A: CSR build ----
    count_kernel<<<gC, T, 0, sA>>>(ei);
    block_sum_kernel<<<NBLK, 1024, 0, sA>>>();
    rowptr_kernel<<<NBLK, 1024, 0, sA>>>();
    csr_fill_kernel<<<gF, T, 0, sA>>>(ei);
    cudaEventRecord(g_sp.evA, sA);

    // ---- branch B: layer-1 GEMM + attention logits ----
    gemm_al_kernel<128, false><<<(NN + 63) / 64, 128, 0, sB>>>(x, W1, a1s, a1d, 0);
    cudaEventRecord(g_sp.evB, sB);

    cudaStreamWaitEvent(s0, g_sp.evA, 0);
    cudaStreamWaitEvent(s0, g_sp.evB, 0);

    // ---- serial layer chain ----
    gat_agg4_kernel<<<gW, T, 0, s0>>>(b1, 0, 1);
    gemm_al_kernel<128, true><<<(NN + 63) / 64, 128, 0, s0>>>(nullptr, W2, a2s, a2d, 4);
    gat_agg4_kernel<<<gW, T, 0, s0>>>(b2, 4, 1);
    gemm_al_kernel<32, true><<<(NN + 127) / 128, 128, 0, s0>>>(nullptr, W3, a3s, a3d, 8);
    gat_agg1_head_kernel<<<gW, T, 0, s0>>>(b3, Wc, bc, out);
}

// round 17
// speedup vs baseline: 1.4360x; 1.0063x over previous
#include <cuda_runtime.h>
#include <cuda_fp16.h>

// Problem constants (fixed by the dataset)
#define NN 50000
#define EE 800000
#define ETOT 850000   // EE + NN self-loops
#define HH 4
#define CC 32
#define HC 128        // HH*CC
#define NBLK ((NN + 1023) / 1024)   // 49 scan blocks
#define EE2 (EE / 2)                // 400000 edge pairs

// ---------------- scratch (device globals: allocation-free) ----------------
// g_lin16 layout for H=4 layers (written by gemm<128>, read by agg4):
//   per node: 32 x uint2; element l = {half2(ch 2l,2l+1), half2(ch 64+2l,64+2l+1)}
// For the H=1 layer (gemm<32> -> agg1) the layout is plain row-major halves.
__device__ __align__(16) __half g_lin16[NN * HC];
__device__ float g_act[NN * HC];
__device__ float g_alsrc[NN * HH];
__device__ float g_aldst[NN * HH];
__device__ __align__(16) float g_gmax[12];
__device__ int   g_csrc[ETOT];
__device__ int   g_rowptr[NN + 1];
__device__ int   g_fill[NN];
__device__ int   g_bsum[64];
__device__ int   g_is64;

// ---------------- streams for fork/join inside graph capture --------------
struct StreamPack {
    cudaStream_t sA, sB;
    cudaEvent_t evFork, evA, evB;
    StreamPack() {
        cudaStreamCreateWithFlags(&sA, cudaStreamNonBlocking);
        cudaStreamCreateWithFlags(&sB, cudaStreamNonBlocking);
        cudaEventCreateWithFlags(&evFork, cudaEventDisableTiming);
        cudaEventCreateWithFlags(&evA, cudaEventDisableTiming);
        cudaEventCreateWithFlags(&evB, cudaEventDisableTiming);
    }
};
static StreamPack g_sp;

__device__ __forceinline__ void atomicMaxF(float* addr, float v) {
    if (v >= 0.f) atomicMax((int*)addr, __float_as_int(v));
    else          atomicMin((unsigned int*)addr, __float_as_uint(v));
}

// ---- packed f32x2 helpers (FFMA2 path, sm_103a) ----
__device__ __forceinline__ unsigned long long pack2(float x) {
    unsigned long long r;
    asm("mov.b64 %0, {%1, %2};" : "=l"(r) : "f"(x), "f"(x));
    return r;
}
__device__ __forceinline__ void fma2(unsigned long long& d, unsigned long long a,
                                     unsigned long long b) {
    asm("fma.rn.f32x2 %0, %1, %2, %0;" : "+l"(d) : "l"(a), "l"(b));
}
__device__ __forceinline__ float2 unpack2(unsigned long long v) {
    float lo, hi;
    asm("mov.b64 {%0, %1}, %2;" : "=f"(lo), "=f"(hi) : "l"(v));
    return make_float2(lo, hi);
}

// ---------------- prologue: is64 detect + gmax init + g_fill = 1 ----------
__global__ void detect_zero_kernel(const int* __restrict__ buf) {
    int t = blockIdx.x * blockDim.x + threadIdx.x;
    if (t < NN) g_fill[t] = 1;
    if (blockIdx.x == 0 && threadIdx.x == 0) {
        int orv = 0;
        #pragma unroll
        for (int i = 1; i < 64; i += 2) orv |= buf[i];
        g_is64 = (orv == 0) ? 1 : 0;
    }
    if (blockIdx.x == 1 && threadIdx.x < 12) g_gmax[threadIdx.x] = -3.0e38f;
}

// degree count: 2 edges per thread, vectorized dst decode
__global__ void count_kernel(const int* __restrict__ buf) {
    int u = blockIdx.x * blockDim.x + threadIdx.x;
    if (u >= EE2) return;
    int d0, d1;
    if (g_is64) {
        int4 v = ((const int4*)buf)[EE2 + u];
        d0 = v.x; d1 = v.z;
    } else {
        int2 v = ((const int2*)(buf + EE))[u];
        d0 = v.x; d1 = v.y;
    }
    atomicAdd(&g_fill[d0], 1);
    atomicAdd(&g_fill[d1], 1);
}

// ---------------- 2-phase coalesced scan ----------------
__global__ void block_sum_kernel() {
    __shared__ int ws[32];
    int tid = threadIdx.x;
    int idx = blockIdx.x * 1024 + tid;
    int v = (idx < NN) ? g_fill[idx] : 0;
    #pragma unroll
    for (int o = 16; o >= 1; o >>= 1) v += __shfl_xor_sync(0xffffffff, v, o);
    int lane = tid & 31, wid = tid >> 5;
    if (lane == 0) ws[wid] = v;
    __syncthreads();
    if (wid == 0) {
        int w = ws[lane];
        #pragma unroll
        for (int o = 16; o >= 1; o >>= 1) w += __shfl_xor_sync(0xffffffff, w, o);
        if (lane == 0) g_bsum[blockIdx.x] = w;
    }
}

__global__ void rowptr_kernel() {
    __shared__ int ws[32];
    __shared__ int bofs;
    int tid = threadIdx.x;
    int idx = blockIdx.x * 1024 + tid;
    int lane = tid & 31, wid = tid >> 5;

    if (wid == 0) {
        int B = blockIdx.x;
        int a = (lane < B) ? g_bsum[lane] : 0;
        int b2 = (lane + 32 < B) ? g_bsum[lane + 32] : 0;
        int v = a + b2;
        #pragma unroll
        for (int o = 16; o >= 1; o >>= 1) v += __shfl_xor_sync(0xffffffff, v, o);
        if (lane == 0) bofs = v;
    }

    int c = (idx < NN) ? g_fill[idx] : 0;
    int v = c;
    #pragma unroll
    for (int o = 1; o < 32; o <<= 1) {
        int t2 = __shfl_up_sync(0xffffffff, v, o);
        if (lane >= o) v += t2;
    }
    if (lane == 31) ws[wid] = v;
    __syncthreads();
    if (wid == 0) {
        int w = ws[lane];
        #pragma unroll
        for (int o = 1; o < 32; o <<= 1) {
            int t2 = __shfl_up_sync(0xffffffff, w, o);
            if (lane >= o) w += t2;
        }
        ws[lane] = w;
    }
    __syncthreads();
    int excl = v - c + (wid > 0 ? ws[wid - 1] : 0) + bofs;
    if (idx < NN) {
        g_rowptr[idx] = excl;
        g_fill[idx] = excl;
    }
    if (idx == 0) g_rowptr[NN] = ETOT;
}

// fill CSR: 2 edges per thread, vectorized decode; self-loops in the tail
__global__ void csr_fill_kernel(const int* __restrict__ buf) {
    int u = blockIdx.x * blockDim.x + threadIdx.x;
    if (u < EE2) {
        int s0, s1, d0, d1;
        if (g_is64) {
            int4 sv = ((const int4*)buf)[u];
            int4 dv = ((const int4*)buf)[EE2 + u];
            s0 = sv.x; s1 = sv.z; d0 = dv.x; d1 = dv.z;
        } else {
            int2 sv = ((const int2*)buf)[u];
            int2 dv = ((const int2*)(buf + EE))[u];
            s0 = sv.x; s1 = sv.y; d0 = dv.x; d1 = dv.y;
        }
        g_csrc[atomicAdd(&g_fill[d0], 1)] = s0;
        g_csrc[atomicAdd(&g_fill[d1], 1)] = s1;
    } else {
        int v = u - EE2;
        if (v < NN) g_csrc[atomicAdd(&g_fill[v], 1)] = v;
    }
}

// ---------------- GEMM (FFMA2) + fused attention logits ----------------
// OUT==128: messages stored INTERLEAVED (see g_lin16 comment). OUT==32: plain.
template<int OUT, bool FROMACT>
__global__ __launch_bounds__(128) void gemm_al_kernel(
        const float* __restrict__ X, const float* __restrict__ W,
        const float* __restrict__ a_src, const float* __restrict__ a_dst,
        int gslot) {
    constexpr int NPB = (OUT == 128) ? 64 : 128;
    constexpr int CPT = (OUT == 128) ? 8 : 4;
    constexpr int CP2 = CPT / 2;
    constexpr int CGN = OUT / CPT;
    constexpr int KC  = 32;
    constexpr int NH  = (OUT == 128) ? 4 : 1;

    __shared__ __align__(16) float Xs[KC][NPB];
    __shared__ __align__(16) float Ws[KC][OUT];
    __shared__ float smax[NH];

    const float* __restrict__ Xp = FROMACT ? g_act : X;
    const int tid = threadIdx.x;
    const int cg = tid % CGN;
    const int ng = tid / CGN;
    const int row0 = blockIdx.x * NPB;

    if (tid < NH) smax[tid] = -3.0e38f;

    unsigned long long acc2[8][CP2];
    #pragma unroll
    for (int i = 0; i < 8; i++)
        #pragma unroll
        for (int j = 0; j < CP2; j++) acc2[i][j] = 0ull;

    for (int kc = 0; kc < HC; kc += KC) {
        __syncthreads();
        #pragma unroll
        for (int e = tid; e < KC * NPB / 4; e += 128) {
            int n  = e / (KC / 4);
            int kq = e % (KC / 4);
            int row = row0 + n; if (row >= NN) row = NN - 1;
            float4 v = *(const float4*)&Xp[row * HC + kc + kq * 4];
            Xs[kq * 4 + 0][n] = v.x;
            Xs[kq * 4 + 1][n] = v.y;
            Xs[kq * 4 + 2][n] = v.z;
            Xs[kq * 4 + 3][n] = v.w;
        }
        #pragma unroll
        for (int e = tid; e < KC * OUT / 4; e += 128) {
            ((float4*)&Ws[0][0])[e] = ((const float4*)&W[kc * OUT])[e];
        }
        __syncthreads();

        #pragma unroll
        for (int k = 0; k < KC; k++) {
            float4 xa = *(const float4*)&Xs[k][ng * 8];
            float4 xb = *(const float4*)&Xs[k][ng * 8 + 4];
            unsigned long long xd[8];
            xd[0] = pack2(xa.x); xd[1] = pack2(xa.y);
            xd[2] = pack2(xa.z); xd[3] = pack2(xa.w);
            xd[4] = pack2(xb.x); xd[5] = pack2(xb.y);
            xd[6] = pack2(xb.z); xd[7] = pack2(xb.w);

            unsigned long long wp[CP2];
            {
                double2 w0 = *(const double2*)&Ws[k][cg * CPT];
                wp[0] = __double_as_longlong(w0.x);
                wp[1] = __double_as_longlong(w0.y);
                if (CP2 == 4) {
                    double2 w1 = *(const double2*)&Ws[k][cg * CPT + 4];
                    wp[2] = __double_as_longlong(w1.x);
                    wp[3] = __double_as_longlong(w1.y);
                }
            }
            #pragma unroll
            for (int i = 0; i < 8; i++)
                #pragma unroll
                for (int j = 0; j < CP2; j++)
                    fma2(acc2[i][j], xd[i], wp[j]);
        }
    }

    float acc[8][CPT];
    #pragma unroll
    for (int i = 0; i < 8; i++)
        #pragma unroll
        for (int j = 0; j < CP2; j++) {
            float2 v = unpack2(acc2[i][j]);
            acc[i][2 * j] = v.x;
            acc[i][2 * j + 1] = v.y;
        }

    // store messages as fp16
    if (OUT == 128) {
        // interleaved layout: pair l lives at rowp[l*4 + 0..1] (first half)
        // or rowp[l*4 + 2..3] (second half, channels 64+)
        const int l0  = (cg & 7) * 4;        // first pair index owned
        const int off = (cg >> 3) * 2;       // 0 = channels [0,64), 2 = [64,128)
        #pragma unroll
        for (int i = 0; i < 8; i++) {
            int row = row0 + ng * 8 + i;
            if (row < NN) {
                __half* rowp = g_lin16 + row * HC;
                #pragma unroll
                for (int q = 0; q < CP2; q++) {
                    __half2 h = __float22half2_rn(make_float2(acc[i][2 * q], acc[i][2 * q + 1]));
                    *(__half2*)&rowp[(l0 + q) * 4 + off] = h;
                }
            }
        }
    } else {
        #pragma unroll
        for (int i = 0; i < 8; i++) {
            int row = row0 + ng * 8 + i;
            if (row < NN) {
                #pragma unroll
                for (int j = 0; j < CP2; j++) {
                    __half2 h = __float22half2_rn(make_float2(acc[i][2 * j], acc[i][2 * j + 1]));
                    *(__half2*)&g_lin16[row * OUT + cg * CPT + 2 * j] = h;
                }
            }
        }
    }

    // ---- fused al ----
    float asv[CPT], adv[CPT];
    {
        float4 a0 = *(const float4*)&a_src[cg * CPT];
        asv[0] = a0.x; asv[1] = a0.y; asv[2] = a0.z; asv[3] = a0.w;
        float4 d0 = *(const float4*)&a_dst[cg * CPT];
        adv[0] = d0.x; adv[1] = d0.y; adv[2] = d0.z; adv[3] = d0.w;
        if (CPT == 8) {
            float4 a1 = *(const float4*)&a_src[cg * CPT + 4];
            asv[4] = a1.x; asv[5] = a1.y; asv[6] = a1.z; asv[7] = a1.w;
            float4 d1 = *(const float4*)&a_dst[cg * CPT + 4];
            adv[4] = d1.x; adv[5] = d1.y; adv[6] = d1.z; adv[7] = d1.w;
        }
    }
    float ssp[8], sdp[8];
    #pragma unroll
    for (int i = 0; i < 8; i++) {
        float ss = 0.f, sd = 0.f;
        #pragma unroll
        for (int j = 0; j < CPT; j++) {
            ss += acc[i][j] * asv[j];
            sd += acc[i][j] * adv[j];
        }
        ssp[i] = ss; sdp[i] = sd;
    }
    #pragma unroll
    for (int i = 0; i < 8; i++) {
        ssp[i] += __shfl_xor_sync(0xffffffff, ssp[i], 1);
        sdp[i] += __shfl_xor_sync(0xffffffff, sdp[i], 1);
        ssp[i] += __shfl_xor_sync(0xffffffff, ssp[i], 2);
        sdp[i] += __shfl_xor_sync(0xffffffff, sdp[i], 2);
        if (OUT == 32) {
            ssp[i] += __shfl_xor_sync(0xffffffff, ssp[i], 4);
            sdp[i] += __shfl_xor_sync(0xffffffff, sdp[i], 4);
        }
    }
    float lmax = -3.0e38f;
    if (OUT == 128) {
        if ((cg & 3) == 0) {
            int h = cg >> 2;
            #pragma unroll
            for (int i = 0; i < 8; i++) {
                int row = row0 + ng * 8 + i;
                if (row < NN) {
                    g_alsrc[row * HH + h] = ssp[i];
                    g_aldst[row * HH + h] = sdp[i];
                    lmax = fmaxf(lmax, ssp[i]);
                }
            }
            atomicMaxF(&smax[h], lmax);
        }
    } else {
        if (cg == 0) {
            #pragma unroll
            for (int i = 0; i < 8; i++) {
                int row = row0 + ng * 8 + i;
                if (row < NN) {
                    g_alsrc[row] = ssp[i];
                    g_aldst[row] = sdp[i];
                    lmax = fmaxf(lmax, ssp[i]);
                }
            }
            atomicMaxF(&smax[0], lmax);
        }
    }
    __syncthreads();
    if (tid < NH) atomicMaxF(&g_gmax[gslot + tid], smax[tid]);
}

// ---------------- single-pass fused GAT aggregation (warp per dst) ----------
// interleaved message layout: ONE uint2 load per edge fetches both head-halves
__global__ __launch_bounds__(256) void gat_agg4_kernel(const float* __restrict__ b,
                                                       int gslot, int do_elu) {
    __shared__ int    ss[8][32];
    __shared__ float4 ww[8][32];

    int warp = (blockIdx.x * blockDim.x + threadIdx.x) >> 5;
    if (warp >= NN) return;
    int lane = threadIdx.x & 31;
    int wslot = (threadIdx.x >> 5) & 7;
    int d = warp;
    int start = g_rowptr[d], end = g_rowptr[d + 1];

    float4 ad = *(const float4*)&g_aldst[d * HH];
    float4 gm = *(const float4*)&g_gmax[gslot];
    float4 m;
    m.x = gm.x + ad.x; m.x = (m.x > 0.f) ? m.x : 0.2f * m.x;
    m.y = gm.y + ad.y; m.y = (m.y > 0.f) ? m.y : 0.2f * m.y;
    m.z = gm.z + ad.z; m.z = (m.z > 0.f) ? m.z : 0.2f * m.z;
    m.w = gm.w + ad.w; m.w = (m.w > 0.f) ? m.w : 0.2f * m.w;

    const int h0 = lane >> 4;
    const int h1 = 2 + h0;

    float4 denom = make_float4(0.f, 0.f, 0.f, 0.f);
    float a0x = 0.f, a0y = 0.f, a1x = 0.f, a1y = 0.f;

    for (int base = start; base < end; base += 32) {
        int i = base + lane;
        float4 w = make_float4(0.f, 0.f, 0.f, 0.f);
        int s = 0;
        if (i < end) {
            s = g_csrc[i];
            float4 v = *(const float4*)&g_alsrc[s * HH];
            v.x += ad.x; v.y += ad.y; v.z += ad.z; v.w += ad.w;
            v.x = (v.x > 0.f) ? v.x : 0.2f * v.x;
            v.y = (v.y > 0.f) ? v.y : 0.2f * v.y;
            v.z = (v.z > 0.f) ? v.z : 0.2f * v.z;
            v.w = (v.w > 0.f) ? v.w : 0.2f * v.w;
            w.x = __expf(v.x - m.x);
            w.y = __expf(v.y - m.y);
            w.z = __expf(v.z - m.z);
            w.w = __expf(v.w - m.w);
        }
        denom.x += w.x; denom.y += w.y; denom.z += w.z; denom.w += w.w;
        ss[wslot][lane] = s;
        ww[wslot][lane] = w;
        __syncwarp();
        int n = min(32, end - base);
        int j = 0;
        // unroll by 8: 8 independent 256B uint2 loads in flight
        for (; j + 7 < n; j += 8) {
            uint2 r[8];
            #pragma unroll
            for (int q = 0; q < 8; q++) {
                const uint2* hp = (const uint2*)(g_lin16 + ss[wslot][j + q] * HC);
                r[q] = hp[lane];
            }
            #pragma unroll
            for (int q = 0; q < 8; q++) {
                const float* wp = (const float*)&ww[wslot][j + q];
                float wa = wp[h0], wb = wp[h1];
                float2 p0 = __half22float2(*(const __half2*)&r[q].x);
                float2 p1 = __half22float2(*(const __half2*)&r[q].y);
                a0x += wa * p0.x; a0y += wa * p0.y;
                a1x += wb * p1.x; a1y += wb * p1.y;
            }
        }
        for (; j + 3 < n; j += 4) {
            uint2 r[4];
            #pragma unroll
            for (int q = 0; q < 4; q++) {
                const uint2* hp = (const uint2*)(g_lin16 + ss[wslot][j + q] * HC);
                r[q] = hp[lane];
            }
            #pragma unroll
            for (int q = 0; q < 4; q++) {
                const float* wp = (const float*)&ww[wslot][j + q];
                float wa = wp[h0], wb = wp[h1];
                float2 p0 = __half22float2(*(const __half2*)&r[q].x);
                float2 p1 = __half22float2(*(const __half2*)&r[q].y);
                a0x += wa * p0.x; a0y += wa * p0.y;
                a1x += wb * p1.x; a1y += wb * p1.y;
            }
        }
        for (; j < n; j++) {
            const uint2* hp = (const uint2*)(g_lin16 + ss[wslot][j] * HC);
            uint2 r = hp[lane];
            const float* wjp = (const float*)&ww[wslot][j];
            float2 m0 = __half22float2(*(const __half2*)&r.x);
            float2 m1 = __half22float2(*(const __half2*)&r.y);
            float w0 = wjp[h0], w1 = wjp[h1];
            a0x += w0 * m0.x; a0y += w0 * m0.y;
            a1x += w1 * m1.x; a1y += w1 * m1.y;
        }
        __syncwarp();
    }

    #pragma unroll
    for (int o = 16; o >= 1; o >>= 1) {
        denom.x += __shfl_xor_sync(0xffffffff, denom.x, o);
        denom.y += __shfl_xor_sync(0xffffffff, denom.y, o);
        denom.z += __shfl_xor_sync(0xffffffff, denom.z, o);
        denom.w += __shfl_xor_sync(0xffffffff, denom.w, o);
    }
    float rd0 = 1.f / ((h0 == 0 ? denom.x : denom.y) + 1e-16f);
    float rd1 = 1.f / ((h1 == 2 ? denom.z : denom.w) + 1e-16f);

    float2 b0 = *(const float2*)&b[2 * lane];
    float2 b1 = *(const float2*)&b[64 + 2 * lane];
    a0x = a0x * rd0 + b0.x;
    a0y = a0y * rd0 + b0.y;
    a1x = a1x * rd1 + b1.x;
    a1y = a1y * rd1 + b1.y;
    if (do_elu) {
        a0x = (a0x > 0.f) ? a0x : (__expf(a0x) - 1.f);
        a0y = (a0y > 0.f) ? a0y : (__expf(a0y) - 1.f);
        a1x = (a1x > 0.f) ? a1x : (__expf(a1x) - 1.f);
        a1y = (a1y > 0.f) ? a1y : (__expf(a1y) - 1.f);
    }
    float* o = g_act + d * HC;
    *(float2*)&o[2 * lane] = make_float2(a0x, a0y);
    *(float2*)&o[64 + 2 * lane] = make_float2(a1x, a1y);
}

// layer 3 (H=1) fused with classifier head + embedding write (plain layout)
__global__ __launch_bounds__(256) void gat_agg1_head_kernel(
        const float* __restrict__ b, const float* __restrict__ Wc,
        const float* __restrict__ bc, float* __restrict__ out) {
    __shared__ int   ss[8][32];
    __shared__ float ww[8][32];

    int warp = (blockIdx.x * blockDim.x + threadIdx.x) >> 5;
    if (warp >= NN) return;
    int lane = threadIdx.x & 31;
    int wslot = (threadIdx.x >> 5) & 7;
    int d = warp;
    int start = g_rowptr[d], end = g_rowptr[d + 1];

    float ad = g_aldst[d];
    float gm = g_gmax[8];
    float m = gm + ad; m = (m > 0.f) ? m : 0.2f * m;

    float denom = 0.f;
    float acc = 0.f;

    for (int base = start; base < end; base += 32) {
        int i = base + lane;
        float w = 0.f;
        int s = 0;
        if (i < end) {
            s = g_csrc[i];
            float v = g_alsrc[s] + ad;
            v = (v > 0.f) ? v : 0.2f * v;
            w = __expf(v - m);
        }
        denom += w;
        ss[wslot][lane] = s;
        ww[wslot][lane] = w;
        __syncwarp();
        int n = min(32, end - base);
        int j = 0;
        for (; j + 7 < n; j += 8) {
            float v[8];
            #pragma unroll
            for (int q = 0; q < 8; q++)
                v[q] = __half2float(g_lin16[ss[wslot][j + q] * CC + lane]);
            #pragma unroll
            for (int q = 0; q < 8; q++)
                acc += ww[wslot][j + q] * v[q];
        }
        for (; j + 3 < n; j += 4) {
            float v0 = __half2float(g_lin16[ss[wslot][j] * CC + lane]);
            float v1 = __half2float(g_lin16[ss[wslot][j + 1] * CC + lane]);
            float v2 = __half2float(g_lin16[ss[wslot][j + 2] * CC + lane]);
            float v3 = __half2float(g_lin16[ss[wslot][j + 3] * CC + lane]);
            acc += ww[wslot][j] * v0 + ww[wslot][j + 1] * v1
                 + ww[wslot][j + 2] * v2 + ww[wslot][j + 3] * v3;
        }
        for (; j < n; j++) {
            acc += ww[wslot][j] * __half2float(g_lin16[ss[wslot][j] * CC + lane]);
        }
        __syncwarp();
    }
    #pragma unroll
    for (int o = 16; o >= 1; o >>= 1)
        denom += __shfl_xor_sync(0xffffffff, denom, o);

    float h = acc / (denom + 1e-16f) + b[lane];

    out[NN * 2 + d * CC + lane] = h;

    float o0 = h * Wc[lane * 2 + 0];
    float o1 = h * Wc[lane * 2 + 1];
    #pragma unroll
    for (int o = 16; o >= 1; o >>= 1) {
        o0 += __shfl_xor_sync(0xffffffff, o0, o);
        o1 += __shfl_xor_sync(0xffffffff, o1, o);
    }
    if (lane == 0) {
        out[d * 2 + 0] = o0 + bc[0];
        out[d * 2 + 1] = o1 + bc[1];
    }
}

// ---------------- launch ----------------
extern "C" void kernel_launch(void* const* d_in, const int* in_sizes, int n_in,
                              void* d_out, int out_size) {
    const float* x   = (const float*)d_in[0];
    const int*   ei  = (const int*)d_in[1];
    const float* W1  = (const float*)d_in[2];
    const float* a1s = (const float*)d_in[3];
    const float* a1d = (const float*)d_in[4];
    const float* b1  = (const float*)d_in[5];
    const float* W2  = (const float*)d_in[6];
    const float* a2s = (const float*)d_in[7];
    const float* a2d = (const float*)d_in[8];
    const float* b2  = (const float*)d_in[9];
    const float* W3  = (const float*)d_in[10];
    const float* a3s = (const float*)d_in[11];
    const float* a3d = (const float*)d_in[12];
    const float* b3  = (const float*)d_in[13];
    const float* Wc  = (const float*)d_in[14];
    const float* bc  = (const float*)d_in[15];
    float* out = (float*)d_out;

    const int T = 256;
    const int gN = (NN + T - 1) / T;
    const int gW = (NN * 32 + T - 1) / T;
    const int gC = (EE2 + T - 1) / T;
    const int gF = (EE2 + NN + T - 1) / T;

    cudaStream_t s0 = 0;
    cudaStream_t sA = g_sp.sA;
    cudaStream_t sB = g_sp.sB;

    detect_zero_kernel<<<gN, T, 0, s0>>>(ei);

    cudaEventRecord(g_sp.evFork, s0);
    cudaStreamWaitEvent(sA, g_sp.evFork, 0);
    cudaStreamWaitEvent(sB, g_sp.evFork, 0);

    // ---- branch A: CSR build ----
    count_kernel<<<gC, T, 0, sA>>>(ei);
    block_sum_kernel<<<NBLK, 1024, 0, sA>>>();
    rowptr_kernel<<<NBLK, 1024, 0, sA>>>();
    csr_fill_kernel<<<gF, T, 0, sA>>>(ei);
    cudaEventRecord(g_sp.evA, sA);

    // ---- branch B: layer-1 GEMM + attention logits ----
    gemm_al_kernel<128, false><<<(NN + 63) / 64, 128, 0, sB>>>(x, W1, a1s, a1d, 0);
    cudaEventRecord(g_sp.evB, sB);

    cudaStreamWaitEvent(s0, g_sp.evA, 0);
    cudaStreamWaitEvent(s0, g_sp.evB, 0);

    // ---- serial layer chain ----
    gat_agg4_kernel<<<gW, T, 0, s0>>>(b1, 0, 1);
    gemm_al_kernel<128, true><<<(NN + 63) / 64, 128, 0, s0>>>(nullptr, W2, a2s, a2d, 4);
    gat_agg4_kernel<<<gW, T, 0, s0>>>(b2, 4, 1);
    gemm_al_kernel<32, true><<<(NN + 127) / 128, 128, 0, s0>>>(nullptr, W3, a3s, a3d, 8);
    gat_agg1_head_kernel<<<gW, T, 0, s0>>>(b3, Wc, bc, out);
}